// round 12
// baseline (speedup 1.0000x reference)
#include <cuda_runtime.h>
#include <math.h>

#define Bsz 2
#define Lsz 1024
#define DM 512
#define DSTATE 16
#define HD 64
#define DI 1024
#define NH 16
#define NL 6
#define FFND 2048
#define CONVD 1056
#define DPROJ 2096
#define ROWS (Bsz*Lsz)   // 2048

typedef unsigned long long ull;

// ---------------- scratch (static __device__, no allocation) ----------------
__device__ float g_xbuf[ROWS*DM];
__device__ float g_s[ROWS*DM];
__device__ float g_zx[2][ROWS*DPROJ];
__device__ float g_xconv[2][ROWS*CONVD];
__device__ float g_dt[2][ROWS*NH];
__device__ float g_dA[2][ROWS*NH];
__device__ float g_y[2][ROWS*DI];
__device__ float g_gbuf[ROWS*2*DI];
__device__ float g_ffnh[ROWS*FFND];

__device__ __forceinline__ float siluf(float x){ return x / (1.0f + expf(-x)); }
__device__ __forceinline__ float gelunf(float x){ return 0.5f*x*(1.0f+erff(x*0.70710678118654752f)); }

__device__ __forceinline__ ull pack2(float a, float b){
    ull r; asm("mov.b64 %0, {%1, %2};" : "=l"(r) : "f"(a), "f"(b)); return r;
}
__device__ __forceinline__ void ffma2(ull &d, ull a, ull b){
    asm("fma.rn.f32x2 %0, %1, %2, %0;" : "+l"(d) : "l"(a), "l"(b));
}
__device__ __forceinline__ float2 unpack2(ull v){
    float2 r; asm("mov.b64 {%0, %1}, %2;" : "=f"(r.x), "=f"(r.y) : "l"(v)); return r;
}

// ---------------- simple copy ----------------
__global__ void copy_k(const float* __restrict__ in, float* __restrict__ out, int n){
    int i = blockIdx.x*blockDim.x + threadIdx.x;
    if (i < n) out[i] = in[i];
}

// ---------------- RMSNorm over 512 dims; optional (+pos)*mask ----------------
__global__ void rms512_k(const float* __restrict__ in, const float* __restrict__ w,
                         const float* __restrict__ pos, const float* __restrict__ mask,
                         float* __restrict__ out, float eps)
{
    int row = blockIdx.x;
    int tid = threadIdx.x;  // 128 threads, float4 each = 512
    const float4 v = ((const float4*)(in + (size_t)row*DM))[tid];
    float ss = v.x*v.x + v.y*v.y + v.z*v.z + v.w*v.w;
    #pragma unroll
    for (int o = 16; o > 0; o >>= 1) ss += __shfl_xor_sync(0xffffffffu, ss, o);
    __shared__ float ws[4];
    if ((tid & 31) == 0) ws[tid >> 5] = ss;
    __syncthreads();
    float tot = ws[0] + ws[1] + ws[2] + ws[3];
    float inv = rsqrtf(tot * (1.0f/DM) + eps);
    const float4 wv = ((const float4*)w)[tid];
    float4 o4;
    o4.x = v.x*inv*wv.x; o4.y = v.y*inv*wv.y; o4.z = v.z*inv*wv.z; o4.w = v.w*inv*wv.w;
    if (pos){
        float m = mask[row];
        const float4 p4 = ((const float4*)(pos + (size_t)row*DM))[tid];
        o4.x = (o4.x + p4.x)*m; o4.y = (o4.y + p4.y)*m;
        o4.z = (o4.z + p4.z)*m; o4.w = (o4.w + p4.w)*m;
    }
    ((float4*)(out + (size_t)row*DM))[tid] = o4;
}

// ---------------- SGEMM BMx128x8, 256 thr, f32x2 packed FMA, double-buffered
// A staged in SMEM pre-duplicated as (a,a) 64-bit pairs -> no per-kk packing.
// B-fragment split at 16B lane stride -> conflict-free LDS.128.
// __launch_bounds__(256,2): <=128 regs, 2 CTAs/SM.
// EPI 0: C = acc
// EPI 1: C = gelu(acc + bias[col])
// EPI 2: C = C + acc + bias[col]          (ffn2 residual, in-place)
// EPI 3: C += scale * extra[row] * acc    (out-proj combine into residual)
template<int EPI, int BM>
__global__ __launch_bounds__(256, 2)
void sgemm_k(const float* __restrict__ A, const float* __restrict__ B,
             float* __restrict__ C, int M, int N, int K,
             const float* __restrict__ bias, const float* __restrict__ extra,
             float scale, long strideB, long strideC)
{
    constexpr int TM = BM/16;          // 8 (BM=128) or 4 (BM=64)
    constexpr int AV = BM/32;          // floats per thread per k-slab for A
    B += (size_t)blockIdx.z * strideB;
    C += (size_t)blockIdx.z * strideC;
    __shared__ __align__(16) ull   As2[2][8][BM];   // duplicated pairs
    __shared__ __align__(16) float Bs[2][8][128];
    const int tid = threadIdx.x;
    const int bx = blockIdx.x, by = blockIdx.y;

    int arow, acol;
    if (BM == 128){ arow = tid >> 1; acol = (tid & 1)*4; }
    else          { arow = tid >> 2; acol = (tid & 3)*2; }
    const int brow = tid >> 5, bcol = (tid & 31)*4;
    const int gcolB = bx*128 + bcol;
    const float* Aptr = A + (size_t)(by*BM + arow)*K + acol;
    const float* Bptr = B + (size_t)brow*N + gcolB;
    const bool bok = (gcolB < N);

    ull acc2[TM][4];
    #pragma unroll
    for (int i = 0; i < TM; i++)
        #pragma unroll
        for (int jp = 0; jp < 4; jp++) acc2[i][jp] = 0ull;

    const int ty = tid >> 4, tx = tid & 15;

    float av[4];
    float4 bv;
    // preload first k-slab
    if (BM == 128){
        float4 t = *(const float4*)Aptr;
        av[0]=t.x; av[1]=t.y; av[2]=t.z; av[3]=t.w;
    } else {
        float2 t = *(const float2*)Aptr;
        av[0]=t.x; av[1]=t.y;
    }
    bv = bok ? *(const float4*)Bptr : make_float4(0.f,0.f,0.f,0.f);
    Aptr += 8; Bptr += (size_t)8*N;
    #pragma unroll
    for (int q = 0; q < AV; q++) As2[0][acol+q][arow] = pack2(av[q], av[q]);
    *(float4*)&Bs[0][brow][bcol] = bv;
    __syncthreads();

    int buf = 0;
    for (int k0 = 8; k0 <= K; k0 += 8){
        const bool has = (k0 < K);
        if (has){
            if (BM == 128){
                float4 t = *(const float4*)Aptr;
                av[0]=t.x; av[1]=t.y; av[2]=t.z; av[3]=t.w;
            } else {
                float2 t = *(const float2*)Aptr;
                av[0]=t.x; av[1]=t.y;
            }
            bv = bok ? *(const float4*)Bptr : make_float4(0.f,0.f,0.f,0.f);
            Aptr += 8; Bptr += (size_t)8*N;
        }
        #pragma unroll
        for (int kk = 0; kk < 8; kk++){
            ull ra2[TM];
            if (BM == 128){
                ulonglong2 a0 = *(const ulonglong2*)&As2[buf][kk][ty*8];
                ulonglong2 a1 = *(const ulonglong2*)&As2[buf][kk][ty*8+2];
                ulonglong2 a2 = *(const ulonglong2*)&As2[buf][kk][ty*8+4];
                ulonglong2 a3 = *(const ulonglong2*)&As2[buf][kk][ty*8+6];
                ra2[0]=a0.x; ra2[1]=a0.y; ra2[2]=a1.x; ra2[3]=a1.y;
                ra2[4]=a2.x; ra2[5]=a2.y; ra2[6]=a3.x; ra2[7]=a3.y;
            } else {
                ulonglong2 a0 = *(const ulonglong2*)&As2[buf][kk][ty*4];
                ulonglong2 a1 = *(const ulonglong2*)&As2[buf][kk][ty*4+2];
                ra2[0]=a0.x; ra2[1]=a0.y; ra2[2]=a1.x; ra2[3]=a1.y;
            }
            // conflict-free: lane stride 16B
            ulonglong2 q0 = *(const ulonglong2*)&Bs[buf][kk][tx*4];
            ulonglong2 q1 = *(const ulonglong2*)&Bs[buf][kk][64 + tx*4];
            ull rb2[4]; rb2[0]=q0.x; rb2[1]=q0.y; rb2[2]=q1.x; rb2[3]=q1.y;
            #pragma unroll
            for (int i = 0; i < TM; i++){
                #pragma unroll
                for (int jp = 0; jp < 4; jp++) ffma2(acc2[i][jp], ra2[i], rb2[jp]);
            }
        }
        if (has){
            #pragma unroll
            for (int q = 0; q < AV; q++) As2[buf^1][acol+q][arow] = pack2(av[q], av[q]);
            *(float4*)&Bs[buf^1][brow][bcol] = bv;
            __syncthreads();
            buf ^= 1;
        }
    }

    const int row0 = by*BM + ty*TM;
    const int cA = bx*128 + tx*4;      // fragment 0: 4 cols
    const int cB = cA + 64;            // fragment 1: 4 cols
    #pragma unroll
    for (int i = 0; i < TM; i++){
        const size_t r = (size_t)(row0 + i);
        float m = 0.f;
        if (EPI == 3) m = scale * extra[r];
        #pragma unroll
        for (int jp = 0; jp < 4; jp++){
            float2 v = unpack2(acc2[i][jp]);
            const int c0 = (jp < 2) ? (cA + jp*2) : (cB + (jp-2)*2);
            if (c0 < N){
                if (EPI == 0)      C[r*N + c0] = v.x;
                else if (EPI == 1) C[r*N + c0] = gelunf(v.x + bias[c0]);
                else if (EPI == 2) C[r*N + c0] = C[r*N + c0] + v.x + bias[c0];
                else               C[r*N + c0] = fmaf(m, v.x, C[r*N + c0]);
            }
            if (c0 + 1 < N){
                if (EPI == 0)      C[r*N + c0+1] = v.y;
                else if (EPI == 1) C[r*N + c0+1] = gelunf(v.y + bias[c0+1]);
                else if (EPI == 2) C[r*N + c0+1] = C[r*N + c0+1] + v.y + bias[c0+1];
                else               C[r*N + c0+1] = fmaf(m, v.y, C[r*N + c0+1]);
            }
        }
    }
}

// ---------------- causal depthwise conv (dir-aware) + SiLU ----------------
__global__ void conv_k(const float* __restrict__ cw, const float* __restrict__ cb)
{
    const int dir = blockIdx.y;
    const int idx = blockIdx.x*blockDim.x + threadIdx.x;
    if (idx >= ROWS*CONVD) return;
    const int row = idx / CONVD, c = idx - row*CONVD;
    const int b = row >> 10, l = row & 1023;
    const float* zx = g_zx[dir];
    const float* w = cw + (size_t)dir*CONVD*4 + (size_t)c*4;
    float acc = cb[dir*CONVD + c];
    #pragma unroll
    for (int k = 0; k < 4; k++){
        int lp = dir ? (l + 3 - k) : (l - 3 + k);
        if (lp >= 0 && lp < Lsz)
            acc = fmaf(w[k], zx[(size_t)(b*Lsz + lp)*DPROJ + DI + c], acc);
    }
    g_xconv[dir][idx] = siluf(acc);
}

// ---------------- dt = softplus(raw + bias); dA = exp(dt * -exp(A_log)) ----
__global__ void dt_k(const float* __restrict__ dtb, const float* __restrict__ Alog)
{
    const int dir = blockIdx.y;
    const int idx = blockIdx.x*blockDim.x + threadIdx.x;
    if (idx >= ROWS*NH) return;
    const int row = idx >> 4, h = idx & 15;
    float raw = g_zx[dir][(size_t)row*DPROJ + DI + CONVD + h] + dtb[dir*NH + h];
    float dt = (raw > 20.f) ? raw : log1pf(expf(raw));
    float A = -expf(Alog[dir*NH + h]);
    g_dt[dir][idx] = dt;
    g_dA[dir][idx] = expf(dt * A);
}

// ---------------- selective scan: block per (dir,b,head), thread per p ------
__global__ __launch_bounds__(64)
void scan_k(const float* __restrict__ Dvec)
{
    const int blk = blockIdx.x;
    const int dir = blk >> 5, b = (blk >> 4) & 1, h = blk & 15;
    const float* xc  = g_xconv[dir];
    const float* dtp = g_dt[dir];
    const float* dAp = g_dA[dir];
    float* yp = g_y[dir];
    const float Dh = Dvec[dir*NH + h];
    const int p = threadIdx.x;
    const int base = b*Lsz;

    __shared__ float sX[64][64];
    __shared__ float sB[64][16], sC[64][16];
    __shared__ float sdA[64], sdt[64];

    float hreg[16];
    #pragma unroll
    for (int j = 0; j < 16; j++) hreg[j] = 0.f;

    for (int t0 = 0; t0 < Lsz; t0 += 64){
        #pragma unroll
        for (int i = 0; i < 16; i++){
            int li = p + i*64;
            int tl = li >> 4, pq = li & 15;
            int grow = base + (dir ? (Lsz-1 - (t0+tl)) : (t0+tl));
            *(float4*)&sX[tl][pq*4] =
                *(const float4*)&xc[(size_t)grow*CONVD + h*HD + pq*4];
        }
        #pragma unroll
        for (int i = 0; i < 4; i++){
            int li = p + i*64;
            int tl = li >> 2, j4 = (li & 3)*4;
            int grow = base + (dir ? (Lsz-1 - (t0+tl)) : (t0+tl));
            *(float4*)&sB[tl][j4] = *(const float4*)&xc[(size_t)grow*CONVD + DI + j4];
            *(float4*)&sC[tl][j4] = *(const float4*)&xc[(size_t)grow*CONVD + DI + DSTATE + j4];
        }
        {
            int grow = base + (dir ? (Lsz-1 - (t0+p)) : (t0+p));
            sdA[p] = dAp[grow*NH + h];
            sdt[p] = dtp[grow*NH + h];
        }
        __syncthreads();

        for (int tl = 0; tl < 64; tl++){
            float a = sdA[tl], d = sdt[tl];
            float x = sX[tl][p];
            float dx = d * x;
            float bb[16], cc[16];
            #pragma unroll
            for (int q = 0; q < 4; q++){
                *(float4*)&bb[q*4] = *(const float4*)&sB[tl][q*4];
                *(float4*)&cc[q*4] = *(const float4*)&sC[tl][q*4];
            }
            float acc = 0.f;
            #pragma unroll
            for (int j = 0; j < 16; j++){
                hreg[j] = hreg[j]*a + dx*bb[j];
                acc = fmaf(hreg[j], cc[j], acc);
            }
            int grow = base + (dir ? (Lsz-1 - (t0+tl)) : (t0+tl));
            yp[(size_t)grow*DI + h*HD + p] = fmaf(Dh, x, acc);
        }
        __syncthreads();
    }
}

// ---------------- gated RMSNorm (1024 dims): g = rms(y*silu(z)) * w ---------
__global__ void gnorm_k(const float* __restrict__ mnw)
{
    const int row = blockIdx.x, dir = blockIdx.y;
    const int tid = threadIdx.x;  // 256 threads x float4 = 1024
    const float4 yv = ((const float4*)(g_y[dir] + (size_t)row*DI))[tid];
    const float4 zv = *(const float4*)(g_zx[dir] + (size_t)row*DPROJ + tid*4);
    float4 v;
    v.x = yv.x * siluf(zv.x);
    v.y = yv.y * siluf(zv.y);
    v.z = yv.z * siluf(zv.z);
    v.w = yv.w * siluf(zv.w);
    float ss = v.x*v.x + v.y*v.y + v.z*v.z + v.w*v.w;
    #pragma unroll
    for (int o = 16; o > 0; o >>= 1) ss += __shfl_xor_sync(0xffffffffu, ss, o);
    __shared__ float ws[8];
    if ((tid & 31) == 0) ws[tid >> 5] = ss;
    __syncthreads();
    float tot = 0.f;
    #pragma unroll
    for (int i = 0; i < 8; i++) tot += ws[i];
    float inv = rsqrtf(tot * (1.0f/DI) + 1e-5f);
    const float4 wv = *(const float4*)(mnw + dir*DI + tid*4);
    float4 o4;
    o4.x = v.x*inv*wv.x; o4.y = v.y*inv*wv.y;
    o4.z = v.z*inv*wv.z; o4.w = v.w*inv*wv.w;
    *(float4*)&g_gbuf[(size_t)row*(2*DI) + dir*DI + tid*4] = o4;
}

// ---------------- launch ----------------
extern "C" void kernel_launch(void* const* d_in, const int* in_sizes, int n_in,
                              void* d_out, int out_size)
{
    const float* x      = (const float*)d_in[0];
    const float* pos    = (const float*)d_in[1];
    const float* mask   = (const float*)d_in[2];
    const float* W_in   = (const float*)d_in[3];
    const float* conv_w = (const float*)d_in[4];
    const float* conv_b = (const float*)d_in[5];
    const float* A_log  = (const float*)d_in[6];
    const float* Dvec   = (const float*)d_in[7];
    const float* dt_b   = (const float*)d_in[8];
    const float* mnw    = (const float*)d_in[9];
    const float* W_out  = (const float*)d_in[10];
    const float* nssm   = (const float*)d_in[11];
    const float* fw1    = (const float*)d_in[12];
    const float* fb1    = (const float*)d_in[13];
    const float* fw2    = (const float*)d_in[14];
    const float* fb2    = (const float*)d_in[15];
    const float* nffn   = (const float*)d_in[16];
    const float* fnw    = (const float*)d_in[17];

    float *xbuf, *s, *zx, *gbuf, *ffnh;
    cudaGetSymbolAddress((void**)&xbuf, g_xbuf);
    cudaGetSymbolAddress((void**)&s,    g_s);
    cudaGetSymbolAddress((void**)&zx,   g_zx);
    cudaGetSymbolAddress((void**)&gbuf, g_gbuf);
    cudaGetSymbolAddress((void**)&ffnh, g_ffnh);

    copy_k<<<(ROWS*DM + 255)/256, 256>>>(x, xbuf, ROWS*DM);

    for (int l = 0; l < NL; l++){
        // s = (rms(x, nssm) + pos) * mask
        rms512_k<<<ROWS, 128>>>(xbuf, nssm + l*DM, pos, mask, s, 1e-6f);
        // zx[dir] = s @ W_in[l,dir]
        sgemm_k<0,128><<<dim3(17, 16, 2), 256>>>(
            s, W_in + (size_t)l*2*DM*DPROJ, zx, ROWS, DPROJ, DM,
            nullptr, nullptr, 0.f, (long)DM*DPROJ, (long)ROWS*DPROJ);
        // conv + silu (both dirs)
        conv_k<<<dim3((ROWS*CONVD + 255)/256, 2), 256>>>(
            conv_w + (size_t)l*2*CONVD*4, conv_b + (size_t)l*2*CONVD);
        // dt / dA
        dt_k<<<dim3((ROWS*NH + 255)/256, 2), 256>>>(
            dt_b + (size_t)l*2*NH, A_log + (size_t)l*2*NH);
        // selective scan (64 chains)
        scan_k<<<64, 64>>>(Dvec + (size_t)l*2*NH);
        // gated norm -> concatenated g
        gnorm_k<<<dim3(ROWS, 2), 256>>>(mnw + (size_t)l*2*DI);
        // x += 0.5*mask*(g @ [W_out_f; W_out_b])   (BM=64: 128 CTAs)
        sgemm_k<3,64><<<dim3(4, 32, 1), 256>>>(
            gbuf, W_out + (size_t)l*2*DI*DM, xbuf, ROWS, DM, 2*DI,
            nullptr, mask, 0.5f, 0, 0);
        // FFN
        rms512_k<<<ROWS, 128>>>(xbuf, nffn + l*DM, nullptr, nullptr, s, 1e-6f);
        sgemm_k<1,128><<<dim3(16, 16, 1), 256>>>(
            s, fw1 + (size_t)l*DM*FFND, ffnh, ROWS, FFND, DM,
            fb1 + (size_t)l*FFND, nullptr, 0.f, 0, 0);
        sgemm_k<2,64><<<dim3(4, 32, 1), 256>>>(
            ffnh, fw2 + (size_t)l*FFND*DM, xbuf, ROWS, DM, FFND,
            fb2 + (size_t)l*DM, nullptr, 0.f, 0, 0);
    }

    rms512_k<<<ROWS, 128>>>(xbuf, fnw, nullptr, nullptr, (float*)d_out, 1e-6f);
}

// round 13
// speedup vs baseline: 1.4080x; 1.4080x over previous
#include <cuda_runtime.h>
#include <math.h>

#define Bsz 2
#define Lsz 1024
#define DM 512
#define DSTATE 16
#define HD 64
#define DI 1024
#define NH 16
#define NL 6
#define FFND 2048
#define CONVD 1056
#define DPROJ 2096
#define ROWS (Bsz*Lsz)   // 2048

typedef unsigned long long ull;

// ---------------- scratch (static __device__, no allocation) ----------------
__device__ float g_xbuf[ROWS*DM];
__device__ float g_s[ROWS*DM];
__device__ float g_zx[2][ROWS*DPROJ];
__device__ float g_xconv[2][ROWS*CONVD];
__device__ float g_dt[2][ROWS*NH];
__device__ float g_dA[2][ROWS*NH];
__device__ float g_y[2][ROWS*DI];
__device__ float g_gbuf[ROWS*2*DI];
__device__ float g_ffnh[ROWS*FFND];

__device__ __forceinline__ float siluf(float x){ return x / (1.0f + expf(-x)); }
__device__ __forceinline__ float gelunf(float x){ return 0.5f*x*(1.0f+erff(x*0.70710678118654752f)); }

__device__ __forceinline__ ull pack2(float a, float b){
    ull r; asm("mov.b64 %0, {%1, %2};" : "=l"(r) : "f"(a), "f"(b)); return r;
}
__device__ __forceinline__ void ffma2(ull &d, ull a, ull b){
    asm("fma.rn.f32x2 %0, %1, %2, %0;" : "+l"(d) : "l"(a), "l"(b));
}
__device__ __forceinline__ float2 unpack2(ull v){
    float2 r; asm("mov.b64 {%0, %1}, %2;" : "=f"(r.x), "=f"(r.y) : "l"(v)); return r;
}

// ---------------- simple copy ----------------
__global__ void copy_k(const float* __restrict__ in, float* __restrict__ out, int n){
    int i = blockIdx.x*blockDim.x + threadIdx.x;
    if (i < n) out[i] = in[i];
}

// ---------------- RMSNorm over 512 dims; optional (+pos)*mask ----------------
__global__ void rms512_k(const float* __restrict__ in, const float* __restrict__ w,
                         const float* __restrict__ pos, const float* __restrict__ mask,
                         float* __restrict__ out, float eps)
{
    int row = blockIdx.x;
    int tid = threadIdx.x;  // 128 threads, float4 each = 512
    const float4 v = ((const float4*)(in + (size_t)row*DM))[tid];
    float ss = v.x*v.x + v.y*v.y + v.z*v.z + v.w*v.w;
    #pragma unroll
    for (int o = 16; o > 0; o >>= 1) ss += __shfl_xor_sync(0xffffffffu, ss, o);
    __shared__ float ws[4];
    if ((tid & 31) == 0) ws[tid >> 5] = ss;
    __syncthreads();
    float tot = ws[0] + ws[1] + ws[2] + ws[3];
    float inv = rsqrtf(tot * (1.0f/DM) + eps);
    const float4 wv = ((const float4*)w)[tid];
    float4 o4;
    o4.x = v.x*inv*wv.x; o4.y = v.y*inv*wv.y; o4.z = v.z*inv*wv.z; o4.w = v.w*inv*wv.w;
    if (pos){
        float m = mask[row];
        const float4 p4 = ((const float4*)(pos + (size_t)row*DM))[tid];
        o4.x = (o4.x + p4.x)*m; o4.y = (o4.y + p4.y)*m;
        o4.z = (o4.z + p4.z)*m; o4.w = (o4.w + p4.w)*m;
    }
    ((float4*)(out + (size_t)row*DM))[tid] = o4;
}

// ---------------- SGEMM BMx128x8, 256 thr, f32x2 packed FMA, double-buffered
// A staged in SMEM pre-duplicated as (a,a) 64-bit pairs -> no per-kk packing.
// B-fragment split at 16B lane stride -> conflict-free LDS.128.
// __launch_bounds__(256): no reg cap (R12 lesson: (256,2) spills).
// EPI 0: C = acc
// EPI 1: C = gelu(acc + bias[col])
// EPI 2: C = C + acc + bias[col]          (ffn2 residual, in-place)
// EPI 3: C += scale * extra[row] * acc    (out-proj combine into residual)
template<int EPI, int BM>
__global__ __launch_bounds__(256)
void sgemm_k(const float* __restrict__ A, const float* __restrict__ B,
             float* __restrict__ C, int M, int N, int K,
             const float* __restrict__ bias, const float* __restrict__ extra,
             float scale, long strideB, long strideC)
{
    constexpr int TM = BM/16;          // 8 (BM=128) or 4 (BM=64)
    constexpr int AV = BM/32;          // floats per thread per k-slab for A
    B += (size_t)blockIdx.z * strideB;
    C += (size_t)blockIdx.z * strideC;
    __shared__ __align__(16) ull   As2[2][8][BM];   // duplicated (a,a) pairs
    __shared__ __align__(16) float Bs[2][8][128];
    const int tid = threadIdx.x;
    const int bx = blockIdx.x, by = blockIdx.y;

    int arow, acol;
    if (BM == 128){ arow = tid >> 1; acol = (tid & 1)*4; }
    else          { arow = tid >> 2; acol = (tid & 3)*2; }
    const int brow = tid >> 5, bcol = (tid & 31)*4;
    const int gcolB = bx*128 + bcol;
    const float* Aptr = A + (size_t)(by*BM + arow)*K + acol;
    const float* Bptr = B + (size_t)brow*N + gcolB;
    const bool bok = (gcolB < N);

    ull acc2[TM][4];
    #pragma unroll
    for (int i = 0; i < TM; i++)
        #pragma unroll
        for (int jp = 0; jp < 4; jp++) acc2[i][jp] = 0ull;

    const int ty = tid >> 4, tx = tid & 15;

    float av[4];
    float4 bv;
    // preload first k-slab
    if (BM == 128){
        float4 t = *(const float4*)Aptr;
        av[0]=t.x; av[1]=t.y; av[2]=t.z; av[3]=t.w;
    } else {
        float2 t = *(const float2*)Aptr;
        av[0]=t.x; av[1]=t.y;
    }
    bv = bok ? *(const float4*)Bptr : make_float4(0.f,0.f,0.f,0.f);
    Aptr += 8; Bptr += (size_t)8*N;
    #pragma unroll
    for (int q = 0; q < AV; q++) As2[0][acol+q][arow] = pack2(av[q], av[q]);
    *(float4*)&Bs[0][brow][bcol] = bv;
    __syncthreads();

    int buf = 0;
    for (int k0 = 8; k0 <= K; k0 += 8){
        const bool has = (k0 < K);
        if (has){
            if (BM == 128){
                float4 t = *(const float4*)Aptr;
                av[0]=t.x; av[1]=t.y; av[2]=t.z; av[3]=t.w;
            } else {
                float2 t = *(const float2*)Aptr;
                av[0]=t.x; av[1]=t.y;
            }
            bv = bok ? *(const float4*)Bptr : make_float4(0.f,0.f,0.f,0.f);
            Aptr += 8; Bptr += (size_t)8*N;
        }
        #pragma unroll
        for (int kk = 0; kk < 8; kk++){
            ull ra2[TM];
            if (BM == 128){
                ulonglong2 a0 = *(const ulonglong2*)&As2[buf][kk][ty*8];
                ulonglong2 a1 = *(const ulonglong2*)&As2[buf][kk][ty*8+2];
                ulonglong2 a2 = *(const ulonglong2*)&As2[buf][kk][ty*8+4];
                ulonglong2 a3 = *(const ulonglong2*)&As2[buf][kk][ty*8+6];
                ra2[0]=a0.x; ra2[1]=a0.y; ra2[2]=a1.x; ra2[3]=a1.y;
                ra2[4]=a2.x; ra2[5]=a2.y; ra2[6]=a3.x; ra2[7]=a3.y;
            } else {
                ulonglong2 a0 = *(const ulonglong2*)&As2[buf][kk][ty*4];
                ulonglong2 a1 = *(const ulonglong2*)&As2[buf][kk][ty*4+2];
                ra2[0]=a0.x; ra2[1]=a0.y; ra2[2]=a1.x; ra2[3]=a1.y;
            }
            // conflict-free: lane stride 16B
            ulonglong2 q0 = *(const ulonglong2*)&Bs[buf][kk][tx*4];
            ulonglong2 q1 = *(const ulonglong2*)&Bs[buf][kk][64 + tx*4];
            ull rb2[4]; rb2[0]=q0.x; rb2[1]=q0.y; rb2[2]=q1.x; rb2[3]=q1.y;
            #pragma unroll
            for (int i = 0; i < TM; i++){
                #pragma unroll
                for (int jp = 0; jp < 4; jp++) ffma2(acc2[i][jp], ra2[i], rb2[jp]);
            }
        }
        if (has){
            #pragma unroll
            for (int q = 0; q < AV; q++) As2[buf^1][acol+q][arow] = pack2(av[q], av[q]);
            *(float4*)&Bs[buf^1][brow][bcol] = bv;
            __syncthreads();
            buf ^= 1;
        }
    }

    const int row0 = by*BM + ty*TM;
    const int cA = bx*128 + tx*4;      // fragment 0: 4 cols
    const int cB = cA + 64;            // fragment 1: 4 cols
    #pragma unroll
    for (int i = 0; i < TM; i++){
        const size_t r = (size_t)(row0 + i);
        float m = 0.f;
        if (EPI == 3) m = scale * extra[r];
        #pragma unroll
        for (int jp = 0; jp < 4; jp++){
            float2 v = unpack2(acc2[i][jp]);
            const int c0 = (jp < 2) ? (cA + jp*2) : (cB + (jp-2)*2);
            if (c0 < N){
                if (EPI == 0)      C[r*N + c0] = v.x;
                else if (EPI == 1) C[r*N + c0] = gelunf(v.x + bias[c0]);
                else if (EPI == 2) C[r*N + c0] = C[r*N + c0] + v.x + bias[c0];
                else               C[r*N + c0] = fmaf(m, v.x, C[r*N + c0]);
            }
            if (c0 + 1 < N){
                if (EPI == 0)      C[r*N + c0+1] = v.y;
                else if (EPI == 1) C[r*N + c0+1] = gelunf(v.y + bias[c0+1]);
                else if (EPI == 2) C[r*N + c0+1] = C[r*N + c0+1] + v.y + bias[c0+1];
                else               C[r*N + c0+1] = fmaf(m, v.y, C[r*N + c0+1]);
            }
        }
    }
}

// ---------------- causal depthwise conv (dir-aware) + SiLU ----------------
__global__ void conv_k(const float* __restrict__ cw, const float* __restrict__ cb)
{
    const int dir = blockIdx.y;
    const int idx = blockIdx.x*blockDim.x + threadIdx.x;
    if (idx >= ROWS*CONVD) return;
    const int row = idx / CONVD, c = idx - row*CONVD;
    const int b = row >> 10, l = row & 1023;
    const float* zx = g_zx[dir];
    const float* w = cw + (size_t)dir*CONVD*4 + (size_t)c*4;
    float acc = cb[dir*CONVD + c];
    #pragma unroll
    for (int k = 0; k < 4; k++){
        int lp = dir ? (l + 3 - k) : (l - 3 + k);
        if (lp >= 0 && lp < Lsz)
            acc = fmaf(w[k], zx[(size_t)(b*Lsz + lp)*DPROJ + DI + c], acc);
    }
    g_xconv[dir][idx] = siluf(acc);
}

// ---------------- dt = softplus(raw + bias); dA = exp(dt * -exp(A_log)) ----
__global__ void dt_k(const float* __restrict__ dtb, const float* __restrict__ Alog)
{
    const int dir = blockIdx.y;
    const int idx = blockIdx.x*blockDim.x + threadIdx.x;
    if (idx >= ROWS*NH) return;
    const int row = idx >> 4, h = idx & 15;
    float raw = g_zx[dir][(size_t)row*DPROJ + DI + CONVD + h] + dtb[dir*NH + h];
    float dt = (raw > 20.f) ? raw : log1pf(expf(raw));
    float A = -expf(Alog[dir*NH + h]);
    g_dt[dir][idx] = dt;
    g_dA[dir][idx] = expf(dt * A);
}

// ---------------- selective scan: block per (dir,b,head), thread per p ------
__global__ __launch_bounds__(64)
void scan_k(const float* __restrict__ Dvec)
{
    const int blk = blockIdx.x;
    const int dir = blk >> 5, b = (blk >> 4) & 1, h = blk & 15;
    const float* xc  = g_xconv[dir];
    const float* dtp = g_dt[dir];
    const float* dAp = g_dA[dir];
    float* yp = g_y[dir];
    const float Dh = Dvec[dir*NH + h];
    const int p = threadIdx.x;
    const int base = b*Lsz;

    __shared__ float sX[64][64];
    __shared__ float sB[64][16], sC[64][16];
    __shared__ float sdA[64], sdt[64];

    float hreg[16];
    #pragma unroll
    for (int j = 0; j < 16; j++) hreg[j] = 0.f;

    for (int t0 = 0; t0 < Lsz; t0 += 64){
        #pragma unroll
        for (int i = 0; i < 16; i++){
            int li = p + i*64;
            int tl = li >> 4, pq = li & 15;
            int grow = base + (dir ? (Lsz-1 - (t0+tl)) : (t0+tl));
            *(float4*)&sX[tl][pq*4] =
                *(const float4*)&xc[(size_t)grow*CONVD + h*HD + pq*4];
        }
        #pragma unroll
        for (int i = 0; i < 4; i++){
            int li = p + i*64;
            int tl = li >> 2, j4 = (li & 3)*4;
            int grow = base + (dir ? (Lsz-1 - (t0+tl)) : (t0+tl));
            *(float4*)&sB[tl][j4] = *(const float4*)&xc[(size_t)grow*CONVD + DI + j4];
            *(float4*)&sC[tl][j4] = *(const float4*)&xc[(size_t)grow*CONVD + DI + DSTATE + j4];
        }
        {
            int grow = base + (dir ? (Lsz-1 - (t0+p)) : (t0+p));
            sdA[p] = dAp[grow*NH + h];
            sdt[p] = dtp[grow*NH + h];
        }
        __syncthreads();

        for (int tl = 0; tl < 64; tl++){
            float a = sdA[tl], d = sdt[tl];
            float x = sX[tl][p];
            float dx = d * x;
            float bb[16], cc[16];
            #pragma unroll
            for (int q = 0; q < 4; q++){
                *(float4*)&bb[q*4] = *(const float4*)&sB[tl][q*4];
                *(float4*)&cc[q*4] = *(const float4*)&sC[tl][q*4];
            }
            float acc = 0.f;
            #pragma unroll
            for (int j = 0; j < 16; j++){
                hreg[j] = hreg[j]*a + dx*bb[j];
                acc = fmaf(hreg[j], cc[j], acc);
            }
            int grow = base + (dir ? (Lsz-1 - (t0+tl)) : (t0+tl));
            yp[(size_t)grow*DI + h*HD + p] = fmaf(Dh, x, acc);
        }
        __syncthreads();
    }
}

// ---------------- gated RMSNorm (1024 dims): g = rms(y*silu(z)) * w ---------
__global__ void gnorm_k(const float* __restrict__ mnw)
{
    const int row = blockIdx.x, dir = blockIdx.y;
    const int tid = threadIdx.x;  // 256 threads x float4 = 1024
    const float4 yv = ((const float4*)(g_y[dir] + (size_t)row*DI))[tid];
    const float4 zv = *(const float4*)(g_zx[dir] + (size_t)row*DPROJ + tid*4);
    float4 v;
    v.x = yv.x * siluf(zv.x);
    v.y = yv.y * siluf(zv.y);
    v.z = yv.z * siluf(zv.z);
    v.w = yv.w * siluf(zv.w);
    float ss = v.x*v.x + v.y*v.y + v.z*v.z + v.w*v.w;
    #pragma unroll
    for (int o = 16; o > 0; o >>= 1) ss += __shfl_xor_sync(0xffffffffu, ss, o);
    __shared__ float ws[8];
    if ((tid & 31) == 0) ws[tid >> 5] = ss;
    __syncthreads();
    float tot = 0.f;
    #pragma unroll
    for (int i = 0; i < 8; i++) tot += ws[i];
    float inv = rsqrtf(tot * (1.0f/DI) + 1e-5f);
    const float4 wv = *(const float4*)(mnw + dir*DI + tid*4);
    float4 o4;
    o4.x = v.x*inv*wv.x; o4.y = v.y*inv*wv.y;
    o4.z = v.z*inv*wv.z; o4.w = v.w*inv*wv.w;
    *(float4*)&g_gbuf[(size_t)row*(2*DI) + dir*DI + tid*4] = o4;
}

// ---------------- launch ----------------
extern "C" void kernel_launch(void* const* d_in, const int* in_sizes, int n_in,
                              void* d_out, int out_size)
{
    const float* x      = (const float*)d_in[0];
    const float* pos    = (const float*)d_in[1];
    const float* mask   = (const float*)d_in[2];
    const float* W_in   = (const float*)d_in[3];
    const float* conv_w = (const float*)d_in[4];
    const float* conv_b = (const float*)d_in[5];
    const float* A_log  = (const float*)d_in[6];
    const float* Dvec   = (const float*)d_in[7];
    const float* dt_b   = (const float*)d_in[8];
    const float* mnw    = (const float*)d_in[9];
    const float* W_out  = (const float*)d_in[10];
    const float* nssm   = (const float*)d_in[11];
    const float* fw1    = (const float*)d_in[12];
    const float* fb1    = (const float*)d_in[13];
    const float* fw2    = (const float*)d_in[14];
    const float* fb2    = (const float*)d_in[15];
    const float* nffn   = (const float*)d_in[16];
    const float* fnw    = (const float*)d_in[17];

    float *xbuf, *s, *zx, *gbuf, *ffnh;
    cudaGetSymbolAddress((void**)&xbuf, g_xbuf);
    cudaGetSymbolAddress((void**)&s,    g_s);
    cudaGetSymbolAddress((void**)&zx,   g_zx);
    cudaGetSymbolAddress((void**)&gbuf, g_gbuf);
    cudaGetSymbolAddress((void**)&ffnh, g_ffnh);

    copy_k<<<(ROWS*DM + 255)/256, 256>>>(x, xbuf, ROWS*DM);

    for (int l = 0; l < NL; l++){
        // s = (rms(x, nssm) + pos) * mask
        rms512_k<<<ROWS, 128>>>(xbuf, nssm + l*DM, pos, mask, s, 1e-6f);
        // zx[dir] = s @ W_in[l,dir]
        sgemm_k<0,128><<<dim3(17, 16, 2), 256>>>(
            s, W_in + (size_t)l*2*DM*DPROJ, zx, ROWS, DPROJ, DM,
            nullptr, nullptr, 0.f, (long)DM*DPROJ, (long)ROWS*DPROJ);
        // conv + silu (both dirs)
        conv_k<<<dim3((ROWS*CONVD + 255)/256, 2), 256>>>(
            conv_w + (size_t)l*2*CONVD*4, conv_b + (size_t)l*2*CONVD);
        // dt / dA
        dt_k<<<dim3((ROWS*NH + 255)/256, 2), 256>>>(
            dt_b + (size_t)l*2*NH, A_log + (size_t)l*2*NH);
        // selective scan (64 chains)
        scan_k<<<64, 64>>>(Dvec + (size_t)l*2*NH);
        // gated norm -> concatenated g
        gnorm_k<<<dim3(ROWS, 2), 256>>>(mnw + (size_t)l*2*DI);
        // x += 0.5*mask*(g @ [W_out_f; W_out_b])   (BM=64: 128 CTAs)
        sgemm_k<3,64><<<dim3(4, 32, 1), 256>>>(
            gbuf, W_out + (size_t)l*2*DI*DM, xbuf, ROWS, DM, 2*DI,
            nullptr, mask, 0.5f, 0, 0);
        // FFN
        rms512_k<<<ROWS, 128>>>(xbuf, nffn + l*DM, nullptr, nullptr, s, 1e-6f);
        sgemm_k<1,128><<<dim3(16, 16, 1), 256>>>(
            s, fw1 + (size_t)l*DM*FFND, ffnh, ROWS, FFND, DM,
            fb1 + (size_t)l*FFND, nullptr, 0.f, 0, 0);
        sgemm_k<2,64><<<dim3(4, 32, 1), 256>>>(
            ffnh, fw2 + (size_t)l*FFND*DM, xbuf, ROWS, DM, FFND,
            fb2 + (size_t)l*DM, nullptr, 0.f, 0, 0);
    }

    rms512_k<<<ROWS, 128>>>(xbuf, fnw, nullptr, nullptr, (float*)d_out, 1e-6f);
}

// round 14
// speedup vs baseline: 1.6123x; 1.1451x over previous
#include <cuda_runtime.h>
#include <math.h>

#define Bsz 2
#define Lsz 1024
#define DM 512
#define DSTATE 16
#define HD 64
#define DI 1024
#define NH 16
#define NL 6
#define FFND 2048
#define CONVD 1056
#define DPROJ 2096
#define ROWS (Bsz*Lsz)   // 2048

typedef unsigned long long ull;

// ---------------- scratch (static __device__, no allocation) ----------------
__device__ float g_xbuf[ROWS*DM];
__device__ float g_s[ROWS*DM];
__device__ float g_zx[2][ROWS*DPROJ];
__device__ float g_xconv[2][ROWS*CONVD];
__device__ float g_dt[2][ROWS*NH];
__device__ float g_dA[2][ROWS*NH];
__device__ float g_y[2][ROWS*DI];
__device__ float g_gbuf[ROWS*2*DI];
__device__ float g_ffnh[ROWS*FFND];

__device__ __forceinline__ float siluf(float x){ return x / (1.0f + expf(-x)); }
__device__ __forceinline__ float gelunf(float x){ return 0.5f*x*(1.0f+erff(x*0.70710678118654752f)); }

__device__ __forceinline__ ull pack2(float a, float b){
    ull r; asm("mov.b64 %0, {%1, %2};" : "=l"(r) : "f"(a), "f"(b)); return r;
}
__device__ __forceinline__ void ffma2(ull &d, ull a, ull b){
    asm("fma.rn.f32x2 %0, %1, %2, %0;" : "+l"(d) : "l"(a), "l"(b));
}
__device__ __forceinline__ float2 unpack2(ull v){
    float2 r; asm("mov.b64 {%0, %1}, %2;" : "=f"(r.x), "=f"(r.y) : "l"(v)); return r;
}

// ---------------- simple copy ----------------
__global__ void copy_k(const float* __restrict__ in, float* __restrict__ out, int n){
    int i = blockIdx.x*blockDim.x + threadIdx.x;
    if (i < n) out[i] = in[i];
}

// ---------------- RMSNorm over 512 dims; optional (+pos)*mask ----------------
__global__ void rms512_k(const float* __restrict__ in, const float* __restrict__ w,
                         const float* __restrict__ pos, const float* __restrict__ mask,
                         float* __restrict__ out, float eps)
{
    int row = blockIdx.x;
    int tid = threadIdx.x;  // 128 threads, float4 each = 512
    const float4 v = ((const float4*)(in + (size_t)row*DM))[tid];
    float ss = v.x*v.x + v.y*v.y + v.z*v.z + v.w*v.w;
    #pragma unroll
    for (int o = 16; o > 0; o >>= 1) ss += __shfl_xor_sync(0xffffffffu, ss, o);
    __shared__ float ws[4];
    if ((tid & 31) == 0) ws[tid >> 5] = ss;
    __syncthreads();
    float tot = ws[0] + ws[1] + ws[2] + ws[3];
    float inv = rsqrtf(tot * (1.0f/DM) + eps);
    const float4 wv = ((const float4*)w)[tid];
    float4 o4;
    o4.x = v.x*inv*wv.x; o4.y = v.y*inv*wv.y; o4.z = v.z*inv*wv.z; o4.w = v.w*inv*wv.w;
    if (pos){
        float m = mask[row];
        const float4 p4 = ((const float4*)(pos + (size_t)row*DM))[tid];
        o4.x = (o4.x + p4.x)*m; o4.y = (o4.y + p4.y)*m;
        o4.z = (o4.z + p4.z)*m; o4.w = (o4.w + p4.w)*m;
    }
    ((float4*)(out + (size_t)row*DM))[tid] = o4;
}

// ---------------- SGEMM BMx128x8, 256 thr, f32x2 packed FMA, double-buffered
// smem double-buffered across slabs; REGISTER fragments double-buffered across
// kk-steps so LDS latency is hidden behind the FFMA2 block.
// B-fragment split at 16B lane stride -> conflict-free LDS.128.
// EPI 0: C = acc
// EPI 1: C = gelu(acc + bias[col])
// EPI 2: C = C + acc + bias[col]          (ffn2 residual, in-place)
// EPI 3: C += scale * extra[row] * acc    (out-proj combine into residual)
template<int EPI, int BM>
__global__ __launch_bounds__(256)
void sgemm_k(const float* __restrict__ A, const float* __restrict__ B,
             float* __restrict__ C, int M, int N, int K,
             const float* __restrict__ bias, const float* __restrict__ extra,
             float scale, long strideB, long strideC)
{
    constexpr int TM = BM/16;          // 8 (BM=128) or 4 (BM=64)
    constexpr int AV = BM/32;          // floats per thread per k-slab for A
    B += (size_t)blockIdx.z * strideB;
    C += (size_t)blockIdx.z * strideC;
    __shared__ __align__(16) float As[2][8][BM];
    __shared__ __align__(16) float Bs[2][8][128];
    const int tid = threadIdx.x;
    const int bx = blockIdx.x, by = blockIdx.y;

    int arow, acol;
    if (BM == 128){ arow = tid >> 1; acol = (tid & 1)*4; }
    else          { arow = tid >> 2; acol = (tid & 3)*2; }
    const int brow = tid >> 5, bcol = (tid & 31)*4;
    const int gcolB = bx*128 + bcol;
    const float* Aptr = A + (size_t)(by*BM + arow)*K + acol;
    const float* Bptr = B + (size_t)brow*N + gcolB;
    const bool bok = (gcolB < N);

    ull acc2[TM][4];
    #pragma unroll
    for (int i = 0; i < TM; i++)
        #pragma unroll
        for (int jp = 0; jp < 4; jp++) acc2[i][jp] = 0ull;

    const int ty = tid >> 4, tx = tid & 15;

    float av[4];
    float4 bv;
    // preload first k-slab
    if (BM == 128){
        float4 t = *(const float4*)Aptr;
        av[0]=t.x; av[1]=t.y; av[2]=t.z; av[3]=t.w;
    } else {
        float2 t = *(const float2*)Aptr;
        av[0]=t.x; av[1]=t.y;
    }
    bv = bok ? *(const float4*)Bptr : make_float4(0.f,0.f,0.f,0.f);
    Aptr += 8; Bptr += (size_t)8*N;
    #pragma unroll
    for (int q = 0; q < AV; q++) As[0][acol+q][arow] = av[q];
    *(float4*)&Bs[0][brow][bcol] = bv;
    __syncthreads();

    // register fragment double-buffer
    ull ra2f[2][TM];
    ull rbf[2][4];

    int buf = 0;
    for (int k0 = 8; k0 <= K; k0 += 8){
        const bool has = (k0 < K);
        if (has){
            if (BM == 128){
                float4 t = *(const float4*)Aptr;
                av[0]=t.x; av[1]=t.y; av[2]=t.z; av[3]=t.w;
            } else {
                float2 t = *(const float2*)Aptr;
                av[0]=t.x; av[1]=t.y;
            }
            bv = bok ? *(const float4*)Bptr : make_float4(0.f,0.f,0.f,0.f);
            Aptr += 8; Bptr += (size_t)8*N;
        }

        // fragment loader: LDS + pack for kk into slot P
        auto load_frag = [&](int P, int kk){
            float ra[TM];
            if (BM == 128){
                *(float4*)&ra[0] = *(const float4*)&As[buf][kk][ty*8];
                *(float4*)&ra[4] = *(const float4*)&As[buf][kk][ty*8+4];
            } else {
                *(float4*)&ra[0] = *(const float4*)&As[buf][kk][ty*4];
            }
            #pragma unroll
            for (int i = 0; i < TM; i++) ra2f[P][i] = pack2(ra[i], ra[i]);
            // conflict-free: lane stride 16B
            ulonglong2 q0 = *(const ulonglong2*)&Bs[buf][kk][tx*4];
            ulonglong2 q1 = *(const ulonglong2*)&Bs[buf][kk][64 + tx*4];
            rbf[P][0]=q0.x; rbf[P][1]=q0.y; rbf[P][2]=q1.x; rbf[P][3]=q1.y;
        };

        load_frag(0, 0);
        #pragma unroll
        for (int kk = 0; kk < 8; kk++){
            const int cur = kk & 1;
            if (kk < 7) load_frag(cur ^ 1, kk + 1);
            #pragma unroll
            for (int i = 0; i < TM; i++){
                #pragma unroll
                for (int jp = 0; jp < 4; jp++)
                    ffma2(acc2[i][jp], ra2f[cur][i], rbf[cur][jp]);
            }
        }

        if (has){
            #pragma unroll
            for (int q = 0; q < AV; q++) As[buf^1][acol+q][arow] = av[q];
            *(float4*)&Bs[buf^1][brow][bcol] = bv;
            __syncthreads();
            buf ^= 1;
        }
    }

    const int row0 = by*BM + ty*TM;
    const int cA = bx*128 + tx*4;      // fragment 0: 4 cols
    const int cB = cA + 64;            // fragment 1: 4 cols
    #pragma unroll
    for (int i = 0; i < TM; i++){
        const size_t r = (size_t)(row0 + i);
        float m = 0.f;
        if (EPI == 3) m = scale * extra[r];
        #pragma unroll
        for (int jp = 0; jp < 4; jp++){
            float2 v = unpack2(acc2[i][jp]);
            const int c0 = (jp < 2) ? (cA + jp*2) : (cB + (jp-2)*2);
            if (c0 < N){
                if (EPI == 0)      C[r*N + c0] = v.x;
                else if (EPI == 1) C[r*N + c0] = gelunf(v.x + bias[c0]);
                else if (EPI == 2) C[r*N + c0] = C[r*N + c0] + v.x + bias[c0];
                else               C[r*N + c0] = fmaf(m, v.x, C[r*N + c0]);
            }
            if (c0 + 1 < N){
                if (EPI == 0)      C[r*N + c0+1] = v.y;
                else if (EPI == 1) C[r*N + c0+1] = gelunf(v.y + bias[c0+1]);
                else if (EPI == 2) C[r*N + c0+1] = C[r*N + c0+1] + v.y + bias[c0+1];
                else               C[r*N + c0+1] = fmaf(m, v.y, C[r*N + c0+1]);
            }
        }
    }
}

// ---------------- causal depthwise conv (dir-aware) + SiLU ----------------
__global__ void conv_k(const float* __restrict__ cw, const float* __restrict__ cb)
{
    const int dir = blockIdx.y;
    const int idx = blockIdx.x*blockDim.x + threadIdx.x;
    if (idx >= ROWS*CONVD) return;
    const int row = idx / CONVD, c = idx - row*CONVD;
    const int b = row >> 10, l = row & 1023;
    const float* zx = g_zx[dir];
    const float* w = cw + (size_t)dir*CONVD*4 + (size_t)c*4;
    float acc = cb[dir*CONVD + c];
    #pragma unroll
    for (int k = 0; k < 4; k++){
        int lp = dir ? (l + 3 - k) : (l - 3 + k);
        if (lp >= 0 && lp < Lsz)
            acc = fmaf(w[k], zx[(size_t)(b*Lsz + lp)*DPROJ + DI + c], acc);
    }
    g_xconv[dir][idx] = siluf(acc);
}

// ---------------- dt = softplus(raw + bias); dA = exp(dt * -exp(A_log)) ----
__global__ void dt_k(const float* __restrict__ dtb, const float* __restrict__ Alog)
{
    const int dir = blockIdx.y;
    const int idx = blockIdx.x*blockDim.x + threadIdx.x;
    if (idx >= ROWS*NH) return;
    const int row = idx >> 4, h = idx & 15;
    float raw = g_zx[dir][(size_t)row*DPROJ + DI + CONVD + h] + dtb[dir*NH + h];
    float dt = (raw > 20.f) ? raw : log1pf(expf(raw));
    float A = -expf(Alog[dir*NH + h]);
    g_dt[dir][idx] = dt;
    g_dA[dir][idx] = expf(dt * A);
}

// ---------------- selective scan: block per (dir,b,head), thread per p ------
__global__ __launch_bounds__(64)
void scan_k(const float* __restrict__ Dvec)
{
    const int blk = blockIdx.x;
    const int dir = blk >> 5, b = (blk >> 4) & 1, h = blk & 15;
    const float* xc  = g_xconv[dir];
    const float* dtp = g_dt[dir];
    const float* dAp = g_dA[dir];
    float* yp = g_y[dir];
    const float Dh = Dvec[dir*NH + h];
    const int p = threadIdx.x;
    const int base = b*Lsz;

    __shared__ float sX[64][64];
    __shared__ float sB[64][16], sC[64][16];
    __shared__ float sdA[64], sdt[64];

    float hreg[16];
    #pragma unroll
    for (int j = 0; j < 16; j++) hreg[j] = 0.f;

    for (int t0 = 0; t0 < Lsz; t0 += 64){
        #pragma unroll
        for (int i = 0; i < 16; i++){
            int li = p + i*64;
            int tl = li >> 4, pq = li & 15;
            int grow = base + (dir ? (Lsz-1 - (t0+tl)) : (t0+tl));
            *(float4*)&sX[tl][pq*4] =
                *(const float4*)&xc[(size_t)grow*CONVD + h*HD + pq*4];
        }
        #pragma unroll
        for (int i = 0; i < 4; i++){
            int li = p + i*64;
            int tl = li >> 2, j4 = (li & 3)*4;
            int grow = base + (dir ? (Lsz-1 - (t0+tl)) : (t0+tl));
            *(float4*)&sB[tl][j4] = *(const float4*)&xc[(size_t)grow*CONVD + DI + j4];
            *(float4*)&sC[tl][j4] = *(const float4*)&xc[(size_t)grow*CONVD + DI + DSTATE + j4];
        }
        {
            int grow = base + (dir ? (Lsz-1 - (t0+p)) : (t0+p));
            sdA[p] = dAp[grow*NH + h];
            sdt[p] = dtp[grow*NH + h];
        }
        __syncthreads();

        for (int tl = 0; tl < 64; tl++){
            float a = sdA[tl], d = sdt[tl];
            float x = sX[tl][p];
            float dx = d * x;
            float bb[16], cc[16];
            #pragma unroll
            for (int q = 0; q < 4; q++){
                *(float4*)&bb[q*4] = *(const float4*)&sB[tl][q*4];
                *(float4*)&cc[q*4] = *(const float4*)&sC[tl][q*4];
            }
            float acc = 0.f;
            #pragma unroll
            for (int j = 0; j < 16; j++){
                hreg[j] = hreg[j]*a + dx*bb[j];
                acc = fmaf(hreg[j], cc[j], acc);
            }
            int grow = base + (dir ? (Lsz-1 - (t0+tl)) : (t0+tl));
            yp[(size_t)grow*DI + h*HD + p] = fmaf(Dh, x, acc);
        }
        __syncthreads();
    }
}

// ---------------- gated RMSNorm (1024 dims): g = rms(y*silu(z)) * w ---------
__global__ void gnorm_k(const float* __restrict__ mnw)
{
    const int row = blockIdx.x, dir = blockIdx.y;
    const int tid = threadIdx.x;  // 256 threads x float4 = 1024
    const float4 yv = ((const float4*)(g_y[dir] + (size_t)row*DI))[tid];
    const float4 zv = *(const float4*)(g_zx[dir] + (size_t)row*DPROJ + tid*4);
    float4 v;
    v.x = yv.x * siluf(zv.x);
    v.y = yv.y * siluf(zv.y);
    v.z = yv.z * siluf(zv.z);
    v.w = yv.w * siluf(zv.w);
    float ss = v.x*v.x + v.y*v.y + v.z*v.z + v.w*v.w;
    #pragma unroll
    for (int o = 16; o > 0; o >>= 1) ss += __shfl_xor_sync(0xffffffffu, ss, o);
    __shared__ float ws[8];
    if ((tid & 31) == 0) ws[tid >> 5] = ss;
    __syncthreads();
    float tot = 0.f;
    #pragma unroll
    for (int i = 0; i < 8; i++) tot += ws[i];
    float inv = rsqrtf(tot * (1.0f/DI) + 1e-5f);
    const float4 wv = *(const float4*)(mnw + dir*DI + tid*4);
    float4 o4;
    o4.x = v.x*inv*wv.x; o4.y = v.y*inv*wv.y;
    o4.z = v.z*inv*wv.z; o4.w = v.w*inv*wv.w;
    *(float4*)&g_gbuf[(size_t)row*(2*DI) + dir*DI + tid*4] = o4;
}

// ---------------- launch ----------------
extern "C" void kernel_launch(void* const* d_in, const int* in_sizes, int n_in,
                              void* d_out, int out_size)
{
    const float* x      = (const float*)d_in[0];
    const float* pos    = (const float*)d_in[1];
    const float* mask   = (const float*)d_in[2];
    const float* W_in   = (const float*)d_in[3];
    const float* conv_w = (const float*)d_in[4];
    const float* conv_b = (const float*)d_in[5];
    const float* A_log  = (const float*)d_in[6];
    const float* Dvec   = (const float*)d_in[7];
    const float* dt_b   = (const float*)d_in[8];
    const float* mnw    = (const float*)d_in[9];
    const float* W_out  = (const float*)d_in[10];
    const float* nssm   = (const float*)d_in[11];
    const float* fw1    = (const float*)d_in[12];
    const float* fb1    = (const float*)d_in[13];
    const float* fw2    = (const float*)d_in[14];
    const float* fb2    = (const float*)d_in[15];
    const float* nffn   = (const float*)d_in[16];
    const float* fnw    = (const float*)d_in[17];

    float *xbuf, *s, *zx, *gbuf, *ffnh;
    cudaGetSymbolAddress((void**)&xbuf, g_xbuf);
    cudaGetSymbolAddress((void**)&s,    g_s);
    cudaGetSymbolAddress((void**)&zx,   g_zx);
    cudaGetSymbolAddress((void**)&gbuf, g_gbuf);
    cudaGetSymbolAddress((void**)&ffnh, g_ffnh);

    copy_k<<<(ROWS*DM + 255)/256, 256>>>(x, xbuf, ROWS*DM);

    for (int l = 0; l < NL; l++){
        // s = (rms(x, nssm) + pos) * mask
        rms512_k<<<ROWS, 128>>>(xbuf, nssm + l*DM, pos, mask, s, 1e-6f);
        // zx[dir] = s @ W_in[l,dir]
        sgemm_k<0,128><<<dim3(17, 16, 2), 256>>>(
            s, W_in + (size_t)l*2*DM*DPROJ, zx, ROWS, DPROJ, DM,
            nullptr, nullptr, 0.f, (long)DM*DPROJ, (long)ROWS*DPROJ);
        // conv + silu (both dirs)
        conv_k<<<dim3((ROWS*CONVD + 255)/256, 2), 256>>>(
            conv_w + (size_t)l*2*CONVD*4, conv_b + (size_t)l*2*CONVD);
        // dt / dA
        dt_k<<<dim3((ROWS*NH + 255)/256, 2), 256>>>(
            dt_b + (size_t)l*2*NH, A_log + (size_t)l*2*NH);
        // selective scan (64 chains)
        scan_k<<<64, 64>>>(Dvec + (size_t)l*2*NH);
        // gated norm -> concatenated g
        gnorm_k<<<dim3(ROWS, 2), 256>>>(mnw + (size_t)l*2*DI);
        // x += 0.5*mask*(g @ [W_out_f; W_out_b])   (BM=64: 128 CTAs)
        sgemm_k<3,64><<<dim3(4, 32, 1), 256>>>(
            gbuf, W_out + (size_t)l*2*DI*DM, xbuf, ROWS, DM, 2*DI,
            nullptr, mask, 0.5f, 0, 0);
        // FFN
        rms512_k<<<ROWS, 128>>>(xbuf, nffn + l*DM, nullptr, nullptr, s, 1e-6f);
        sgemm_k<1,128><<<dim3(16, 16, 1), 256>>>(
            s, fw1 + (size_t)l*DM*FFND, ffnh, ROWS, FFND, DM,
            fb1 + (size_t)l*FFND, nullptr, 0.f, 0, 0);
        sgemm_k<2,64><<<dim3(4, 32, 1), 256>>>(
            ffnh, fw2 + (size_t)l*FFND*DM, xbuf, ROWS, DM, FFND,
            fb2 + (size_t)l*DM, nullptr, 0.f, 0, 0);
    }

    rms512_k<<<ROWS, 128>>>(xbuf, fnw, nullptr, nullptr, (float*)d_out, 1e-6f);
}

// round 15
// speedup vs baseline: 3.5264x; 2.1872x over previous
#include <cuda_runtime.h>
#include <cuda_bf16.h>
#include <math.h>

#define Bsz 2
#define Lsz 1024
#define DM 512
#define DSTATE 16
#define HD 64
#define DI 1024
#define NH 16
#define NL 6
#define FFND 2048
#define CONVD 1056
#define DPROJ 2096
#define ROWS (Bsz*Lsz)   // 2048

// ---------------- scratch (static __device__, no allocation) ----------------
__device__ float g_xbuf[ROWS*DM];
__device__ float g_s[ROWS*DM];
__device__ float g_zx[2][ROWS*DPROJ];
__device__ float g_xconv[2][ROWS*CONVD];
__device__ float g_dt[2][ROWS*NH];
__device__ float g_dA[2][ROWS*NH];
__device__ float g_y[2][ROWS*DI];
__device__ float g_gbuf[ROWS*2*DI];
__device__ float g_ffnh[ROWS*FFND];

__device__ __forceinline__ float siluf(float x){ return x / (1.0f + expf(-x)); }
__device__ __forceinline__ float gelunf(float x){ return 0.5f*x*(1.0f+erff(x*0.70710678118654752f)); }

__device__ __forceinline__ unsigned sa_u32(const void* p){
    unsigned a;
    asm("{ .reg .u64 t; cvta.to.shared.u64 t, %1; cvt.u32.u64 %0, t; }" : "=r"(a) : "l"(p));
    return a;
}
__device__ __forceinline__ void ldmx4(unsigned* r, unsigned a){
    asm volatile("ldmatrix.sync.aligned.m8n8.x4.shared.b16 {%0,%1,%2,%3}, [%4];"
        : "=r"(r[0]),"=r"(r[1]),"=r"(r[2]),"=r"(r[3]) : "r"(a));
}
__device__ __forceinline__ void ldmx4t(unsigned* r, unsigned a){
    asm volatile("ldmatrix.sync.aligned.m8n8.x4.trans.shared.b16 {%0,%1,%2,%3}, [%4];"
        : "=r"(r[0]),"=r"(r[1]),"=r"(r[2]),"=r"(r[3]) : "r"(a));
}
__device__ __forceinline__ void mma16816(float* d, const unsigned* a, const unsigned* b){
    asm volatile("mma.sync.aligned.m16n8k16.row.col.f32.bf16.bf16.f32 "
        "{%0,%1,%2,%3},{%4,%5,%6,%7},{%8,%9},{%0,%1,%2,%3};"
        : "+f"(d[0]),"+f"(d[1]),"+f"(d[2]),"+f"(d[3])
        : "r"(a[0]),"r"(a[1]),"r"(a[2]),"r"(a[3]), "r"(b[0]),"r"(b[1]));
}
// convert 4 fp32 -> (hi,lo) bf16 and store 8B to each tile
__device__ __forceinline__ void cvt_store4(__nv_bfloat16* ph, __nv_bfloat16* pl, float4 v){
    __nv_bfloat16 h0=__float2bfloat16(v.x), h1=__float2bfloat16(v.y),
                  h2=__float2bfloat16(v.z), h3=__float2bfloat16(v.w);
    __nv_bfloat16 l0=__float2bfloat16(v.x-__bfloat162float(h0)),
                  l1=__float2bfloat16(v.y-__bfloat162float(h1)),
                  l2=__float2bfloat16(v.z-__bfloat162float(h2)),
                  l3=__float2bfloat16(v.w-__bfloat162float(h3));
    *(__nv_bfloat162*)(ph)   = __halves2bfloat162(h0,h1);
    *(__nv_bfloat162*)(ph+2) = __halves2bfloat162(h2,h3);
    *(__nv_bfloat162*)(pl)   = __halves2bfloat162(l0,l1);
    *(__nv_bfloat162*)(pl+2) = __halves2bfloat162(l2,l3);
}

// ---------------- simple copy ----------------
__global__ void copy_k(const float* __restrict__ in, float* __restrict__ out, int n){
    int i = blockIdx.x*blockDim.x + threadIdx.x;
    if (i < n) out[i] = in[i];
}

// ---------------- RMSNorm over 512 dims; optional (+pos)*mask ----------------
__global__ void rms512_k(const float* __restrict__ in, const float* __restrict__ w,
                         const float* __restrict__ pos, const float* __restrict__ mask,
                         float* __restrict__ out, float eps)
{
    int row = blockIdx.x;
    int tid = threadIdx.x;  // 128 threads, float4 each = 512
    const float4 v = ((const float4*)(in + (size_t)row*DM))[tid];
    float ss = v.x*v.x + v.y*v.y + v.z*v.z + v.w*v.w;
    #pragma unroll
    for (int o = 16; o > 0; o >>= 1) ss += __shfl_xor_sync(0xffffffffu, ss, o);
    __shared__ float ws[4];
    if ((tid & 31) == 0) ws[tid >> 5] = ss;
    __syncthreads();
    float tot = ws[0] + ws[1] + ws[2] + ws[3];
    float inv = rsqrtf(tot * (1.0f/DM) + eps);
    const float4 wv = ((const float4*)w)[tid];
    float4 o4;
    o4.x = v.x*inv*wv.x; o4.y = v.y*inv*wv.y; o4.z = v.z*inv*wv.z; o4.w = v.w*inv*wv.w;
    if (pos){
        float m = mask[row];
        const float4 p4 = ((const float4*)(pos + (size_t)row*DM))[tid];
        o4.x = (o4.x + p4.x)*m; o4.y = (o4.y + p4.y)*m;
        o4.z = (o4.z + p4.z)*m; o4.w = (o4.w + p4.w)*m;
    }
    ((float4*)(out + (size_t)row*DM))[tid] = o4;
}

// ---------------- tensor-core GEMM: C = A @ B via bf16 3-split --------------
// A fp32 [M,K] row-major, B fp32 [K,N] row-major. 128xBN tiles, BK=32,
// 256 thr = 8 warps (2x4), warp tile 64 x BN/4. mma.sync m16n8k16 bf16.
// A staged K-major (stride 40 halves = 80B, odd*16B -> ldmatrix conflict-free)
// B staged row-major (stride BN+8 halves, odd*16B -> ldmatrix.trans conflict-free)
// EPI 0: C=acc  1: C=gelu(acc+bias)  2: C+=acc+bias  3: C+=scale*extra[row]*acc
template<int EPI, int BN>
__global__ __launch_bounds__(256)
void tgemm_k(const float* __restrict__ A, const float* __restrict__ Bg,
             float* __restrict__ C, int M, int N, int K,
             const float* __restrict__ bias, const float* __restrict__ extra,
             float scale, long strideB, long strideC)
{
    constexpr int BM = 128, BK = 32;
    constexpr int AP = BK + 8;        // 40 halves per A row (80B)
    constexpr int BP = BN + 8;        // 136/72 halves per B row (272/144B)
    constexpr int WNW = BN/4;         // warp n-width 32/16
    constexpr int NF  = WNW/8;        // n-fragments per warp 4/2
    constexpr int NP  = NF/2;         // trans-ldmatrix count 2/1
    constexpr int TPR = BN/4;         // threads per B k-row 32/16
    constexpr int RP  = 256/TPR;      // B k-rows per pass 8/16
    constexpr int BITER = BK/RP;      // 4/2

    Bg += (size_t)blockIdx.z * strideB;
    C  += (size_t)blockIdx.z * strideC;

    __shared__ __align__(16) __nv_bfloat16 Ahs[BM*AP], Als[BM*AP];
    __shared__ __align__(16) __nv_bfloat16 Bhs[BK*BP], Bls[BK*BP];

    const int tid = threadIdx.x, lane = tid & 31, wid = tid >> 5;
    const int wm = wid >> 2, wn = wid & 3, g = lane >> 2, tg = lane & 3;
    const int bx = blockIdx.x, by = blockIdx.y;

    // staging coords
    const int am = tid >> 3, ak = (tid & 7)*4;       // A: 32 rows/pass x 8 float4
    const int bkr = tid / TPR, bn4 = (tid % TPR)*4;  // B
    const int gn = bx*BN + bn4;
    const bool full = (bx*BN + BN <= N);

    float d[4][NF][4];
    #pragma unroll
    for (int mf=0; mf<4; mf++)
        #pragma unroll
        for (int nf=0; nf<NF; nf++)
            #pragma unroll
            for (int q=0; q<4; q++) d[mf][nf][q] = 0.f;

    const float* Ab = A + (size_t)(by*BM + am)*K + ak;

    float4 avA[4], avB[BITER];
    #pragma unroll
    for (int r=0; r<4; r++) avA[r] = *(const float4*)(Ab + (size_t)r*32*K);
    #pragma unroll
    for (int r=0; r<BITER; r++){
        int kk = bkr + r*RP;
        if (full) avB[r] = *(const float4*)&Bg[(size_t)kk*N + gn];
        else {
            const float* p = &Bg[(size_t)kk*N];
            avB[r].x = (gn+0<N)?p[gn+0]:0.f; avB[r].y = (gn+1<N)?p[gn+1]:0.f;
            avB[r].z = (gn+2<N)?p[gn+2]:0.f; avB[r].w = (gn+3<N)?p[gn+3]:0.f;
        }
    }

    const unsigned ah_base = sa_u32(Ahs), al_base = sa_u32(Als);
    const unsigned bh_base = sa_u32(Bhs), bl_base = sa_u32(Bls);
    const int lrow = (lane & 7) + ((lane >> 3) & 1)*8;  // ldmatrix row-within-16
    const int lcol = (lane >> 4)*16;                    // ldmatrix 16B col sel

    for (int k0 = 0; k0 < K; k0 += BK){
        // commit staged regs -> smem (hi/lo conversion fused)
        #pragma unroll
        for (int r=0; r<4; r++)
            cvt_store4(&Ahs[(am + r*32)*AP + ak], &Als[(am + r*32)*AP + ak], avA[r]);
        #pragma unroll
        for (int r=0; r<BITER; r++)
            cvt_store4(&Bhs[(bkr + r*RP)*BP + bn4], &Bls[(bkr + r*RP)*BP + bn4], avB[r]);
        __syncthreads();

        // prefetch next chunk behind the MMA phase
        if (k0 + BK < K){
            #pragma unroll
            for (int r=0; r<4; r++) avA[r] = *(const float4*)(Ab + (k0+BK) + (size_t)r*32*K);
            #pragma unroll
            for (int r=0; r<BITER; r++){
                int kk = k0 + BK + bkr + r*RP;
                if (full) avB[r] = *(const float4*)&Bg[(size_t)kk*N + gn];
                else {
                    const float* p = &Bg[(size_t)kk*N];
                    avB[r].x = (gn+0<N)?p[gn+0]:0.f; avB[r].y = (gn+1<N)?p[gn+1]:0.f;
                    avB[r].z = (gn+2<N)?p[gn+2]:0.f; avB[r].w = (gn+3<N)?p[gn+3]:0.f;
                }
            }
        }

        #pragma unroll
        for (int ks=0; ks<2; ks++){
            unsigned ah[4][4], al[4][4], bh[NF][2], bl[NF][2];
            #pragma unroll
            for (int mf=0; mf<4; mf++){
                unsigned off = (unsigned)((wm*64 + mf*16 + lrow)*(AP*2) + ks*32 + lcol);
                ldmx4(ah[mf], ah_base + off);
            }
            #pragma unroll
            for (int np=0; np<NP; np++){
                unsigned off = (unsigned)((ks*16 + lrow)*(BP*2) + wn*WNW*2 + np*32 + lcol);
                unsigned rr[4]; ldmx4t(rr, bh_base + off);
                bh[2*np][0]=rr[0]; bh[2*np][1]=rr[1];
                bh[2*np+1][0]=rr[2]; bh[2*np+1][1]=rr[3];
            }
            #pragma unroll
            for (int mf=0; mf<4; mf++)
                #pragma unroll
                for (int nf=0; nf<NF; nf++) mma16816(d[mf][nf], ah[mf], bh[nf]);

            #pragma unroll
            for (int mf=0; mf<4; mf++){
                unsigned off = (unsigned)((wm*64 + mf*16 + lrow)*(AP*2) + ks*32 + lcol);
                ldmx4(al[mf], al_base + off);
            }
            #pragma unroll
            for (int mf=0; mf<4; mf++)
                #pragma unroll
                for (int nf=0; nf<NF; nf++) mma16816(d[mf][nf], al[mf], bh[nf]);

            #pragma unroll
            for (int np=0; np<NP; np++){
                unsigned off = (unsigned)((ks*16 + lrow)*(BP*2) + wn*WNW*2 + np*32 + lcol);
                unsigned rr[4]; ldmx4t(rr, bl_base + off);
                bl[2*np][0]=rr[0]; bl[2*np][1]=rr[1];
                bl[2*np+1][0]=rr[2]; bl[2*np+1][1]=rr[3];
            }
            #pragma unroll
            for (int mf=0; mf<4; mf++)
                #pragma unroll
                for (int nf=0; nf<NF; nf++) mma16816(d[mf][nf], ah[mf], bl[nf]);
        }
        __syncthreads();
    }

    // epilogue: thread owns rows (row0, row0+8), col pair (col, col+1)
    #pragma unroll
    for (int mf=0; mf<4; mf++){
        const int row0 = by*BM + wm*64 + mf*16 + g;
        #pragma unroll
        for (int nf=0; nf<NF; nf++){
            const int col = bx*BN + wn*WNW + nf*8 + tg*2;
            if (col < N){
                #pragma unroll
                for (int h=0; h<2; h++){
                    const int r = row0 + h*8;
                    const float x0 = d[mf][nf][h*2], x1 = d[mf][nf][h*2+1];
                    const size_t base = (size_t)r*N + col;
                    if (EPI == 0){ C[base] = x0; C[base+1] = x1; }
                    else if (EPI == 1){
                        C[base]   = gelunf(x0 + bias[col]);
                        C[base+1] = gelunf(x1 + bias[col+1]);
                    } else if (EPI == 2){
                        C[base]   = C[base]   + x0 + bias[col];
                        C[base+1] = C[base+1] + x1 + bias[col+1];
                    } else {
                        const float m = scale * extra[r];
                        C[base]   = fmaf(m, x0, C[base]);
                        C[base+1] = fmaf(m, x1, C[base+1]);
                    }
                }
            }
        }
    }
}

// ---------------- causal depthwise conv (dir-aware) + SiLU ----------------
__global__ void conv_k(const float* __restrict__ cw, const float* __restrict__ cb)
{
    const int dir = blockIdx.y;
    const int idx = blockIdx.x*blockDim.x + threadIdx.x;
    if (idx >= ROWS*CONVD) return;
    const int row = idx / CONVD, c = idx - row*CONVD;
    const int b = row >> 10, l = row & 1023;
    const float* zx = g_zx[dir];
    const float* w = cw + (size_t)dir*CONVD*4 + (size_t)c*4;
    float acc = cb[dir*CONVD + c];
    #pragma unroll
    for (int k = 0; k < 4; k++){
        int lp = dir ? (l + 3 - k) : (l - 3 + k);
        if (lp >= 0 && lp < Lsz)
            acc = fmaf(w[k], zx[(size_t)(b*Lsz + lp)*DPROJ + DI + c], acc);
    }
    g_xconv[dir][idx] = siluf(acc);
}

// ---------------- dt = softplus(raw + bias); dA = exp(dt * -exp(A_log)) ----
__global__ void dt_k(const float* __restrict__ dtb, const float* __restrict__ Alog)
{
    const int dir = blockIdx.y;
    const int idx = blockIdx.x*blockDim.x + threadIdx.x;
    if (idx >= ROWS*NH) return;
    const int row = idx >> 4, h = idx & 15;
    float raw = g_zx[dir][(size_t)row*DPROJ + DI + CONVD + h] + dtb[dir*NH + h];
    float dt = (raw > 20.f) ? raw : log1pf(expf(raw));
    float A = -expf(Alog[dir*NH + h]);
    g_dt[dir][idx] = dt;
    g_dA[dir][idx] = expf(dt * A);
}

// ---------------- selective scan: block per (dir,b,head), thread per p ------
__global__ __launch_bounds__(64)
void scan_k(const float* __restrict__ Dvec)
{
    const int blk = blockIdx.x;
    const int dir = blk >> 5, b = (blk >> 4) & 1, h = blk & 15;
    const float* xc  = g_xconv[dir];
    const float* dtp = g_dt[dir];
    const float* dAp = g_dA[dir];
    float* yp = g_y[dir];
    const float Dh = Dvec[dir*NH + h];
    const int p = threadIdx.x;
    const int base = b*Lsz;

    __shared__ float sX[64][64];
    __shared__ float sB[64][16], sC[64][16];
    __shared__ float sdA[64], sdt[64];

    float hreg[16];
    #pragma unroll
    for (int j = 0; j < 16; j++) hreg[j] = 0.f;

    for (int t0 = 0; t0 < Lsz; t0 += 64){
        #pragma unroll
        for (int i = 0; i < 16; i++){
            int li = p + i*64;
            int tl = li >> 4, pq = li & 15;
            int grow = base + (dir ? (Lsz-1 - (t0+tl)) : (t0+tl));
            *(float4*)&sX[tl][pq*4] =
                *(const float4*)&xc[(size_t)grow*CONVD + h*HD + pq*4];
        }
        #pragma unroll
        for (int i = 0; i < 4; i++){
            int li = p + i*64;
            int tl = li >> 2, j4 = (li & 3)*4;
            int grow = base + (dir ? (Lsz-1 - (t0+tl)) : (t0+tl));
            *(float4*)&sB[tl][j4] = *(const float4*)&xc[(size_t)grow*CONVD + DI + j4];
            *(float4*)&sC[tl][j4] = *(const float4*)&xc[(size_t)grow*CONVD + DI + DSTATE + j4];
        }
        {
            int grow = base + (dir ? (Lsz-1 - (t0+p)) : (t0+p));
            sdA[p] = dAp[grow*NH + h];
            sdt[p] = dtp[grow*NH + h];
        }
        __syncthreads();

        for (int tl = 0; tl < 64; tl++){
            float a = sdA[tl], d = sdt[tl];
            float x = sX[tl][p];
            float dx = d * x;
            float bb[16], cc[16];
            #pragma unroll
            for (int q = 0; q < 4; q++){
                *(float4*)&bb[q*4] = *(const float4*)&sB[tl][q*4];
                *(float4*)&cc[q*4] = *(const float4*)&sC[tl][q*4];
            }
            float acc = 0.f;
            #pragma unroll
            for (int j = 0; j < 16; j++){
                hreg[j] = hreg[j]*a + dx*bb[j];
                acc = fmaf(hreg[j], cc[j], acc);
            }
            int grow = base + (dir ? (Lsz-1 - (t0+tl)) : (t0+tl));
            yp[(size_t)grow*DI + h*HD + p] = fmaf(Dh, x, acc);
        }
        __syncthreads();
    }
}

// ---------------- gated RMSNorm (1024 dims): g = rms(y*silu(z)) * w ---------
__global__ void gnorm_k(const float* __restrict__ mnw)
{
    const int row = blockIdx.x, dir = blockIdx.y;
    const int tid = threadIdx.x;  // 256 threads x float4 = 1024
    const float4 yv = ((const float4*)(g_y[dir] + (size_t)row*DI))[tid];
    const float4 zv = *(const float4*)(g_zx[dir] + (size_t)row*DPROJ + tid*4);
    float4 v;
    v.x = yv.x * siluf(zv.x);
    v.y = yv.y * siluf(zv.y);
    v.z = yv.z * siluf(zv.z);
    v.w = yv.w * siluf(zv.w);
    float ss = v.x*v.x + v.y*v.y + v.z*v.z + v.w*v.w;
    #pragma unroll
    for (int o = 16; o > 0; o >>= 1) ss += __shfl_xor_sync(0xffffffffu, ss, o);
    __shared__ float ws[8];
    if ((tid & 31) == 0) ws[tid >> 5] = ss;
    __syncthreads();
    float tot = 0.f;
    #pragma unroll
    for (int i = 0; i < 8; i++) tot += ws[i];
    float inv = rsqrtf(tot * (1.0f/DI) + 1e-5f);
    const float4 wv = *(const float4*)(mnw + dir*DI + tid*4);
    float4 o4;
    o4.x = v.x*inv*wv.x; o4.y = v.y*inv*wv.y;
    o4.z = v.z*inv*wv.z; o4.w = v.w*inv*wv.w;
    *(float4*)&g_gbuf[(size_t)row*(2*DI) + dir*DI + tid*4] = o4;
}

// ---------------- launch ----------------
extern "C" void kernel_launch(void* const* d_in, const int* in_sizes, int n_in,
                              void* d_out, int out_size)
{
    const float* x      = (const float*)d_in[0];
    const float* pos    = (const float*)d_in[1];
    const float* mask   = (const float*)d_in[2];
    const float* W_in   = (const float*)d_in[3];
    const float* conv_w = (const float*)d_in[4];
    const float* conv_b = (const float*)d_in[5];
    const float* A_log  = (const float*)d_in[6];
    const float* Dvec   = (const float*)d_in[7];
    const float* dt_b   = (const float*)d_in[8];
    const float* mnw    = (const float*)d_in[9];
    const float* W_out  = (const float*)d_in[10];
    const float* nssm   = (const float*)d_in[11];
    const float* fw1    = (const float*)d_in[12];
    const float* fb1    = (const float*)d_in[13];
    const float* fw2    = (const float*)d_in[14];
    const float* fb2    = (const float*)d_in[15];
    const float* nffn   = (const float*)d_in[16];
    const float* fnw    = (const float*)d_in[17];

    float *xbuf, *s, *zx, *gbuf, *ffnh;
    cudaGetSymbolAddress((void**)&xbuf, g_xbuf);
    cudaGetSymbolAddress((void**)&s,    g_s);
    cudaGetSymbolAddress((void**)&zx,   g_zx);
    cudaGetSymbolAddress((void**)&gbuf, g_gbuf);
    cudaGetSymbolAddress((void**)&ffnh, g_ffnh);

    copy_k<<<(ROWS*DM + 255)/256, 256>>>(x, xbuf, ROWS*DM);

    for (int l = 0; l < NL; l++){
        // s = (rms(x, nssm) + pos) * mask
        rms512_k<<<ROWS, 128>>>(xbuf, nssm + l*DM, pos, mask, s, 1e-6f);
        // zx[dir] = s @ W_in[l,dir]   (N=2096, 17 partial-guarded tiles)
        tgemm_k<0,128><<<dim3(17, 16, 2), 256>>>(
            s, W_in + (size_t)l*2*DM*DPROJ, zx, ROWS, DPROJ, DM,
            nullptr, nullptr, 0.f, (long)DM*DPROJ, (long)ROWS*DPROJ);
        // conv + silu (both dirs)
        conv_k<<<dim3((ROWS*CONVD + 255)/256, 2), 256>>>(
            conv_w + (size_t)l*2*CONVD*4, conv_b + (size_t)l*2*CONVD);
        // dt / dA
        dt_k<<<dim3((ROWS*NH + 255)/256, 2), 256>>>(
            dt_b + (size_t)l*2*NH, A_log + (size_t)l*2*NH);
        // selective scan (64 chains)
        scan_k<<<64, 64>>>(Dvec + (size_t)l*2*NH);
        // gated norm -> concatenated g
        gnorm_k<<<dim3(ROWS, 2), 256>>>(mnw + (size_t)l*2*DI);
        // x += 0.5*mask*(g @ [W_out_f; W_out_b])   (BN=64 -> 128 CTAs)
        tgemm_k<3,64><<<dim3(8, 16, 1), 256>>>(
            gbuf, W_out + (size_t)l*2*DI*DM, xbuf, ROWS, DM, 2*DI,
            nullptr, mask, 0.5f, 0, 0);
        // FFN
        rms512_k<<<ROWS, 128>>>(xbuf, nffn + l*DM, nullptr, nullptr, s, 1e-6f);
        tgemm_k<1,128><<<dim3(16, 16, 1), 256>>>(
            s, fw1 + (size_t)l*DM*FFND, ffnh, ROWS, FFND, DM,
            fb1 + (size_t)l*FFND, nullptr, 0.f, 0, 0);
        tgemm_k<2,64><<<dim3(8, 16, 1), 256>>>(
            ffnh, fw2 + (size_t)l*FFND*DM, xbuf, ROWS, DM, FFND,
            fb2 + (size_t)l*DM, nullptr, 0.f, 0, 0);
    }

    rms512_k<<<ROWS, 128>>>(xbuf, fnw, nullptr, nullptr, (float*)d_out, 1e-6f);
}

// round 16
// speedup vs baseline: 3.6358x; 1.0310x over previous
#include <cuda_runtime.h>
#include <cuda_bf16.h>
#include <math.h>

#define Bsz 2
#define Lsz 1024
#define DM 512
#define DSTATE 16
#define HD 64
#define DI 1024
#define NH 16
#define NL 6
#define FFND 2048
#define CONVD 1056
#define DPROJ 2096
#define ROWS (Bsz*Lsz)   // 2048

// ---------------- scratch (static __device__, no allocation) ----------------
__device__ float g_xbuf[ROWS*DM];
__device__ float g_zx[2][ROWS*DPROJ];
__device__ float g_xconv[2][ROWS*CONVD];
__device__ float g_dt[2][ROWS*NH];
__device__ float g_dA[2][ROWS*NH];
__device__ float g_y[2][ROWS*DI];

// bf16 hi/lo activation buffers (GEMM operands)
__device__ __nv_bfloat16 g_sh[ROWS*DM],    g_sl[ROWS*DM];
__device__ __nv_bfloat16 g_gh[ROWS*2*DI],  g_gl[ROWS*2*DI];
__device__ __nv_bfloat16 g_fh[ROWS*FFND],  g_fl[ROWS*FFND];
// bf16 hi/lo weights (converted once per launch)
__device__ __nv_bfloat16 g_wih[NL*2*DM*DPROJ], g_wil[NL*2*DM*DPROJ];
__device__ __nv_bfloat16 g_woh[NL*2*DI*DM],    g_wol[NL*2*DI*DM];
__device__ __nv_bfloat16 g_f1h[NL*DM*FFND],    g_f1l[NL*DM*FFND];
__device__ __nv_bfloat16 g_f2h[NL*FFND*DM],    g_f2l[NL*FFND*DM];

__device__ __forceinline__ float siluf(float x){ return x / (1.0f + expf(-x)); }
__device__ __forceinline__ float gelunf(float x){ return 0.5f*x*(1.0f+erff(x*0.70710678118654752f)); }

__device__ __forceinline__ unsigned sa_u32(const void* p){
    unsigned a;
    asm("{ .reg .u64 t; cvta.to.shared.u64 t, %1; cvt.u32.u64 %0, t; }" : "=r"(a) : "l"(p));
    return a;
}
__device__ __forceinline__ void ldmx4(unsigned* r, unsigned a){
    asm volatile("ldmatrix.sync.aligned.m8n8.x4.shared.b16 {%0,%1,%2,%3}, [%4];"
        : "=r"(r[0]),"=r"(r[1]),"=r"(r[2]),"=r"(r[3]) : "r"(a));
}
__device__ __forceinline__ void ldmx4t(unsigned* r, unsigned a){
    asm volatile("ldmatrix.sync.aligned.m8n8.x4.trans.shared.b16 {%0,%1,%2,%3}, [%4];"
        : "=r"(r[0]),"=r"(r[1]),"=r"(r[2]),"=r"(r[3]) : "r"(a));
}
__device__ __forceinline__ void mma16816(float* d, const unsigned* a, const unsigned* b){
    asm volatile("mma.sync.aligned.m16n8k16.row.col.f32.bf16.bf16.f32 "
        "{%0,%1,%2,%3},{%4,%5,%6,%7},{%8,%9},{%0,%1,%2,%3};"
        : "+f"(d[0]),"+f"(d[1]),"+f"(d[2]),"+f"(d[3])
        : "r"(a[0]),"r"(a[1]),"r"(a[2]),"r"(a[3]), "r"(b[0]),"r"(b[1]));
}
__device__ __forceinline__ void split2(float v, __nv_bfloat16& h, __nv_bfloat16& l){
    h = __float2bfloat16(v);
    l = __float2bfloat16(v - __bfloat162float(h));
}

// ---------------- simple copy ----------------
__global__ void copy_k(const float* __restrict__ in, float* __restrict__ out, int n){
    int i = blockIdx.x*blockDim.x + threadIdx.x;
    if (i < n) out[i] = in[i];
}

// ---------------- weight fp32 -> bf16 hi/lo (vectorized, grid-stride) -------
__global__ void wcvt_k(const float* __restrict__ src,
                       __nv_bfloat16* __restrict__ dh, __nv_bfloat16* __restrict__ dl,
                       int n4)
{
    for (int i = blockIdx.x*blockDim.x + threadIdx.x; i < n4; i += gridDim.x*blockDim.x){
        float4 v = ((const float4*)src)[i];
        __nv_bfloat16 h0,h1,h2,h3,l0,l1,l2,l3;
        split2(v.x,h0,l0); split2(v.y,h1,l1); split2(v.z,h2,l2); split2(v.w,h3,l3);
        ((__nv_bfloat162*)dh)[i*2]   = __halves2bfloat162(h0,h1);
        ((__nv_bfloat162*)dh)[i*2+1] = __halves2bfloat162(h2,h3);
        ((__nv_bfloat162*)dl)[i*2]   = __halves2bfloat162(l0,l1);
        ((__nv_bfloat162*)dl)[i*2+1] = __halves2bfloat162(l2,l3);
    }
}

// ---------------- RMSNorm 512; out fp32 OR bf16 hi/lo; optional (+pos)*mask -
__global__ void rms512_k(const float* __restrict__ in, const float* __restrict__ w,
                         const float* __restrict__ pos, const float* __restrict__ mask,
                         float* __restrict__ outf,
                         __nv_bfloat16* __restrict__ outh, __nv_bfloat16* __restrict__ outl,
                         float eps)
{
    int row = blockIdx.x;
    int tid = threadIdx.x;  // 128 threads, float4 each = 512
    const float4 v = ((const float4*)(in + (size_t)row*DM))[tid];
    float ss = v.x*v.x + v.y*v.y + v.z*v.z + v.w*v.w;
    #pragma unroll
    for (int o = 16; o > 0; o >>= 1) ss += __shfl_xor_sync(0xffffffffu, ss, o);
    __shared__ float ws[4];
    if ((tid & 31) == 0) ws[tid >> 5] = ss;
    __syncthreads();
    float tot = ws[0] + ws[1] + ws[2] + ws[3];
    float inv = rsqrtf(tot * (1.0f/DM) + eps);
    const float4 wv = ((const float4*)w)[tid];
    float4 o4;
    o4.x = v.x*inv*wv.x; o4.y = v.y*inv*wv.y; o4.z = v.z*inv*wv.z; o4.w = v.w*inv*wv.w;
    if (pos){
        float m = mask[row];
        const float4 p4 = ((const float4*)(pos + (size_t)row*DM))[tid];
        o4.x = (o4.x + p4.x)*m; o4.y = (o4.y + p4.y)*m;
        o4.z = (o4.z + p4.z)*m; o4.w = (o4.w + p4.w)*m;
    }
    if (outf) ((float4*)(outf + (size_t)row*DM))[tid] = o4;
    if (outh){
        __nv_bfloat16 h0,h1,h2,h3,l0,l1,l2,l3;
        split2(o4.x,h0,l0); split2(o4.y,h1,l1); split2(o4.z,h2,l2); split2(o4.w,h3,l3);
        size_t base = (size_t)row*DM + tid*4;
        *(__nv_bfloat162*)&outh[base]   = __halves2bfloat162(h0,h1);
        *(__nv_bfloat162*)&outh[base+2] = __halves2bfloat162(h2,h3);
        *(__nv_bfloat162*)&outl[base]   = __halves2bfloat162(l0,l1);
        *(__nv_bfloat162*)&outl[base+2] = __halves2bfloat162(l2,l3);
    }
}

// ---------------- tensor-core GEMM on pre-split bf16 operands ---------------
// A bf16 [M,K] (hi,lo), B bf16 [K,N] (hi,lo). 128xBN tiles, BK=32, 8 warps.
// 3-split: Ah*Bh + Al*Bh + Ah*Bl, fp32 accumulate.
// EPI 0: C=acc  1: Fh/Fl = split(gelu(acc+bias))  2: C+=acc+bias
// EPI 3: C += scale*extra[row]*acc
template<int EPI, int BN>
__global__ __launch_bounds__(256)
void tg2_k(const __nv_bfloat16* __restrict__ Ah, const __nv_bfloat16* __restrict__ Al,
           const __nv_bfloat16* __restrict__ Bh, const __nv_bfloat16* __restrict__ Bl,
           float* __restrict__ C,
           __nv_bfloat16* __restrict__ Fh, __nv_bfloat16* __restrict__ Fl,
           int M, int N, int K,
           const float* __restrict__ bias, const float* __restrict__ extra,
           float scale, long strideB, long strideC)
{
    constexpr int BM = 128, BK = 32;
    constexpr int AP = BK + 8;        // 40 halves per A row (80B)
    constexpr int BP = BN + 8;        // 136/72 halves per B row
    constexpr int WNW = BN/4, NF = WNW/8, NP = NF/2;
    constexpr int BRP = (BN==128) ? 16 : 32;   // B k-rows per pass
    constexpr int BPASS = BK/BRP;              // 2 or 1

    Bh += (size_t)blockIdx.z * strideB;
    Bl += (size_t)blockIdx.z * strideB;
    C  += (size_t)blockIdx.z * strideC;

    __shared__ __align__(16) __nv_bfloat16 Ahs[BM*AP], Als[BM*AP];
    __shared__ __align__(16) __nv_bfloat16 Bhs[BK*BP], Bls[BK*BP];

    const int tid = threadIdx.x, lane = tid & 31, wid = tid >> 5;
    const int wm = wid >> 2, wn = wid & 3, g = lane >> 2, tg = lane & 3;
    const int bx = blockIdx.x, by = blockIdx.y;

    // staging coords: A 64 rows/pass x 4 groups of 8; B BRP rows/pass x BN/8 groups
    const int arow = tid >> 2, acol8 = (tid & 3)*8;
    const int brow = (BN==128) ? (tid >> 4) : (tid >> 3);
    const int bcol8 = ((BN==128) ? (tid & 15) : (tid & 7))*8;
    const int gn = bx*BN + bcol8;
    const bool bok = (gn < N);   // N % 8 == 0 for all call sites

    float d[4][NF][4];
    #pragma unroll
    for (int mf=0; mf<4; mf++)
        #pragma unroll
        for (int nf=0; nf<NF; nf++)
            #pragma unroll
            for (int q=0; q<4; q++) d[mf][nf][q] = 0.f;

    const uint4 zr = make_uint4(0,0,0,0);
    uint4 pAh[2], pAl[2], pBh[BPASS], pBl[BPASS];

    #pragma unroll
    for (int r=0; r<2; r++){
        size_t off = (size_t)(by*BM + arow + r*64)*K + acol8;
        pAh[r] = *(const uint4*)&Ah[off];
        pAl[r] = *(const uint4*)&Al[off];
    }
    #pragma unroll
    for (int r=0; r<BPASS; r++){
        size_t off = (size_t)(brow + r*BRP)*N + gn;
        pBh[r] = bok ? *(const uint4*)&Bh[off] : zr;
        pBl[r] = bok ? *(const uint4*)&Bl[off] : zr;
    }

    const unsigned ah_base = sa_u32(Ahs), al_base = sa_u32(Als);
    const unsigned bh_base = sa_u32(Bhs), bl_base = sa_u32(Bls);
    const int lrow = (lane & 7) + ((lane >> 3) & 1)*8;
    const int lcol = (lane >> 4)*16;

    for (int k0 = 0; k0 < K; k0 += BK){
        // commit staged regs -> smem
        #pragma unroll
        for (int r=0; r<2; r++){
            *(uint4*)&Ahs[(arow + r*64)*AP + acol8] = pAh[r];
            *(uint4*)&Als[(arow + r*64)*AP + acol8] = pAl[r];
        }
        #pragma unroll
        for (int r=0; r<BPASS; r++){
            *(uint4*)&Bhs[(brow + r*BRP)*BP + bcol8] = pBh[r];
            *(uint4*)&Bls[(brow + r*BRP)*BP + bcol8] = pBl[r];
        }
        __syncthreads();

        // prefetch next chunk behind the MMA phase
        if (k0 + BK < K){
            #pragma unroll
            for (int r=0; r<2; r++){
                size_t off = (size_t)(by*BM + arow + r*64)*K + (k0+BK) + acol8;
                pAh[r] = *(const uint4*)&Ah[off];
                pAl[r] = *(const uint4*)&Al[off];
            }
            #pragma unroll
            for (int r=0; r<BPASS; r++){
                size_t off = (size_t)(k0 + BK + brow + r*BRP)*N + gn;
                pBh[r] = bok ? *(const uint4*)&Bh[off] : zr;
                pBl[r] = bok ? *(const uint4*)&Bl[off] : zr;
            }
        }

        #pragma unroll
        for (int ks=0; ks<2; ks++){
            unsigned ah[4][4], al[4][4], bh[NF][2], bl[NF][2];
            #pragma unroll
            for (int mf=0; mf<4; mf++){
                unsigned off = (unsigned)((wm*64 + mf*16 + lrow)*(AP*2) + ks*32 + lcol);
                ldmx4(ah[mf], ah_base + off);
            }
            #pragma unroll
            for (int np=0; np<NP; np++){
                unsigned off = (unsigned)((ks*16 + lrow)*(BP*2) + wn*WNW*2 + np*32 + lcol);
                unsigned rr[4]; ldmx4t(rr, bh_base + off);
                bh[2*np][0]=rr[0]; bh[2*np][1]=rr[1];
                bh[2*np+1][0]=rr[2]; bh[2*np+1][1]=rr[3];
            }
            #pragma unroll
            for (int mf=0; mf<4; mf++)
                #pragma unroll
                for (int nf=0; nf<NF; nf++) mma16816(d[mf][nf], ah[mf], bh[nf]);

            #pragma unroll
            for (int mf=0; mf<4; mf++){
                unsigned off = (unsigned)((wm*64 + mf*16 + lrow)*(AP*2) + ks*32 + lcol);
                ldmx4(al[mf], al_base + off);
            }
            #pragma unroll
            for (int mf=0; mf<4; mf++)
                #pragma unroll
                for (int nf=0; nf<NF; nf++) mma16816(d[mf][nf], al[mf], bh[nf]);

            #pragma unroll
            for (int np=0; np<NP; np++){
                unsigned off = (unsigned)((ks*16 + lrow)*(BP*2) + wn*WNW*2 + np*32 + lcol);
                unsigned rr[4]; ldmx4t(rr, bl_base + off);
                bl[2*np][0]=rr[0]; bl[2*np][1]=rr[1];
                bl[2*np+1][0]=rr[2]; bl[2*np+1][1]=rr[3];
            }
            #pragma unroll
            for (int mf=0; mf<4; mf++)
                #pragma unroll
                for (int nf=0; nf<NF; nf++) mma16816(d[mf][nf], ah[mf], bl[nf]);
        }
        __syncthreads();
    }

    // epilogue: thread owns rows (row0, row0+8), col pair (col, col+1)
    #pragma unroll
    for (int mf=0; mf<4; mf++){
        const int row0 = by*BM + wm*64 + mf*16 + g;
        #pragma unroll
        for (int nf=0; nf<NF; nf++){
            const int col = bx*BN + wn*WNW + nf*8 + tg*2;
            if (col < N){
                #pragma unroll
                for (int h=0; h<2; h++){
                    const int r = row0 + h*8;
                    const float x0 = d[mf][nf][h*2], x1 = d[mf][nf][h*2+1];
                    const size_t base = (size_t)r*N + col;
                    if (EPI == 0){ C[base] = x0; C[base+1] = x1; }
                    else if (EPI == 1){
                        float g0 = gelunf(x0 + bias[col]);
                        float g1 = gelunf(x1 + bias[col+1]);
                        __nv_bfloat16 h0,h1,l0,l1;
                        split2(g0,h0,l0); split2(g1,h1,l1);
                        *(__nv_bfloat162*)&Fh[base] = __halves2bfloat162(h0,h1);
                        *(__nv_bfloat162*)&Fl[base] = __halves2bfloat162(l0,l1);
                    } else if (EPI == 2){
                        C[base]   = C[base]   + x0 + bias[col];
                        C[base+1] = C[base+1] + x1 + bias[col+1];
                    } else {
                        const float m = scale * extra[r];
                        C[base]   = fmaf(m, x0, C[base]);
                        C[base+1] = fmaf(m, x1, C[base+1]);
                    }
                }
            }
        }
    }
}

// ---------------- causal depthwise conv (dir-aware) + SiLU ----------------
__global__ void conv_k(const float* __restrict__ cw, const float* __restrict__ cb)
{
    const int dir = blockIdx.y;
    const int idx = blockIdx.x*blockDim.x + threadIdx.x;
    if (idx >= ROWS*CONVD) return;
    const int row = idx / CONVD, c = idx - row*CONVD;
    const int b = row >> 10, l = row & 1023;
    const float* zx = g_zx[dir];
    const float* w = cw + (size_t)dir*CONVD*4 + (size_t)c*4;
    float acc = cb[dir*CONVD + c];
    #pragma unroll
    for (int k = 0; k < 4; k++){
        int lp = dir ? (l + 3 - k) : (l - 3 + k);
        if (lp >= 0 && lp < Lsz)
            acc = fmaf(w[k], zx[(size_t)(b*Lsz + lp)*DPROJ + DI + c], acc);
    }
    g_xconv[dir][idx] = siluf(acc);
}

// ---------------- dt = softplus(raw + bias); dA = exp(dt * -exp(A_log)) ----
__global__ void dt_k(const float* __restrict__ dtb, const float* __restrict__ Alog)
{
    const int dir = blockIdx.y;
    const int idx = blockIdx.x*blockDim.x + threadIdx.x;
    if (idx >= ROWS*NH) return;
    const int row = idx >> 4, h = idx & 15;
    float raw = g_zx[dir][(size_t)row*DPROJ + DI + CONVD + h] + dtb[dir*NH + h];
    float dt = (raw > 20.f) ? raw : log1pf(expf(raw));
    float A = -expf(Alog[dir*NH + h]);
    g_dt[dir][idx] = dt;
    g_dA[dir][idx] = expf(dt * A);
}

// ---------------- selective scan: block per (dir,b,head), thread per p ------
__global__ __launch_bounds__(64)
void scan_k(const float* __restrict__ Dvec)
{
    const int blk = blockIdx.x;
    const int dir = blk >> 5, b = (blk >> 4) & 1, h = blk & 15;
    const float* xc  = g_xconv[dir];
    const float* dtp = g_dt[dir];
    const float* dAp = g_dA[dir];
    float* yp = g_y[dir];
    const float Dh = Dvec[dir*NH + h];
    const int p = threadIdx.x;
    const int base = b*Lsz;

    __shared__ float sX[64][64];
    __shared__ float sB[64][16], sC[64][16];
    __shared__ float sdA[64], sdt[64];

    float hreg[16];
    #pragma unroll
    for (int j = 0; j < 16; j++) hreg[j] = 0.f;

    for (int t0 = 0; t0 < Lsz; t0 += 64){
        #pragma unroll
        for (int i = 0; i < 16; i++){
            int li = p + i*64;
            int tl = li >> 4, pq = li & 15;
            int grow = base + (dir ? (Lsz-1 - (t0+tl)) : (t0+tl));
            *(float4*)&sX[tl][pq*4] =
                *(const float4*)&xc[(size_t)grow*CONVD + h*HD + pq*4];
        }
        #pragma unroll
        for (int i = 0; i < 4; i++){
            int li = p + i*64;
            int tl = li >> 2, j4 = (li & 3)*4;
            int grow = base + (dir ? (Lsz-1 - (t0+tl)) : (t0+tl));
            *(float4*)&sB[tl][j4] = *(const float4*)&xc[(size_t)grow*CONVD + DI + j4];
            *(float4*)&sC[tl][j4] = *(const float4*)&xc[(size_t)grow*CONVD + DI + DSTATE + j4];
        }
        {
            int grow = base + (dir ? (Lsz-1 - (t0+p)) : (t0+p));
            sdA[p] = dAp[grow*NH + h];
            sdt[p] = dtp[grow*NH + h];
        }
        __syncthreads();

        for (int tl = 0; tl < 64; tl++){
            float a = sdA[tl], d = sdt[tl];
            float x = sX[tl][p];
            float dx = d * x;
            float bb[16], cc[16];
            #pragma unroll
            for (int q = 0; q < 4; q++){
                *(float4*)&bb[q*4] = *(const float4*)&sB[tl][q*4];
                *(float4*)&cc[q*4] = *(const float4*)&sC[tl][q*4];
            }
            float acc = 0.f;
            #pragma unroll
            for (int j = 0; j < 16; j++){
                hreg[j] = hreg[j]*a + dx*bb[j];
                acc = fmaf(hreg[j], cc[j], acc);
            }
            int grow = base + (dir ? (Lsz-1 - (t0+tl)) : (t0+tl));
            yp[(size_t)grow*DI + h*HD + p] = fmaf(Dh, x, acc);
        }
        __syncthreads();
    }
}

// ---------------- gated RMSNorm (1024): g = rms(y*silu(z))*w -> bf16 hi/lo --
__global__ void gnorm_k(const float* __restrict__ mnw)
{
    const int row = blockIdx.x, dir = blockIdx.y;
    const int tid = threadIdx.x;  // 256 threads x float4 = 1024
    const float4 yv = ((const float4*)(g_y[dir] + (size_t)row*DI))[tid];
    const float4 zv = *(const float4*)(g_zx[dir] + (size_t)row*DPROJ + tid*4);
    float4 v;
    v.x = yv.x * siluf(zv.x);
    v.y = yv.y * siluf(zv.y);
    v.z = yv.z * siluf(zv.z);
    v.w = yv.w * siluf(zv.w);
    float ss = v.x*v.x + v.y*v.y + v.z*v.z + v.w*v.w;
    #pragma unroll
    for (int o = 16; o > 0; o >>= 1) ss += __shfl_xor_sync(0xffffffffu, ss, o);
    __shared__ float ws[8];
    if ((tid & 31) == 0) ws[tid >> 5] = ss;
    __syncthreads();
    float tot = 0.f;
    #pragma unroll
    for (int i = 0; i < 8; i++) tot += ws[i];
    float inv = rsqrtf(tot * (1.0f/DI) + 1e-5f);
    const float4 wv = *(const float4*)(mnw + dir*DI + tid*4);
    float4 o4;
    o4.x = v.x*inv*wv.x; o4.y = v.y*inv*wv.y;
    o4.z = v.z*inv*wv.z; o4.w = v.w*inv*wv.w;
    __nv_bfloat16 h0,h1,h2,h3,l0,l1,l2,l3;
    split2(o4.x,h0,l0); split2(o4.y,h1,l1); split2(o4.z,h2,l2); split2(o4.w,h3,l3);
    size_t base = (size_t)row*(2*DI) + dir*DI + tid*4;
    *(__nv_bfloat162*)&g_gh[base]   = __halves2bfloat162(h0,h1);
    *(__nv_bfloat162*)&g_gh[base+2] = __halves2bfloat162(h2,h3);
    *(__nv_bfloat162*)&g_gl[base]   = __halves2bfloat162(l0,l1);
    *(__nv_bfloat162*)&g_gl[base+2] = __halves2bfloat162(l2,l3);
}

// ---------------- launch ----------------
extern "C" void kernel_launch(void* const* d_in, const int* in_sizes, int n_in,
                              void* d_out, int out_size)
{
    const float* x      = (const float*)d_in[0];
    const float* pos    = (const float*)d_in[1];
    const float* mask   = (const float*)d_in[2];
    const float* W_in   = (const float*)d_in[3];
    const float* conv_w = (const float*)d_in[4];
    const float* conv_b = (const float*)d_in[5];
    const float* A_log  = (const float*)d_in[6];
    const float* Dvec   = (const float*)d_in[7];
    const float* dt_b   = (const float*)d_in[8];
    const float* mnw    = (const float*)d_in[9];
    const float* W_out  = (const float*)d_in[10];
    const float* nssm   = (const float*)d_in[11];
    const float* fw1    = (const float*)d_in[12];
    const float* fb1    = (const float*)d_in[13];
    const float* fw2    = (const float*)d_in[14];
    const float* fb2    = (const float*)d_in[15];
    const float* nffn   = (const float*)d_in[16];
    const float* fnw    = (const float*)d_in[17];

    float *xbuf, *zx;
    __nv_bfloat16 *sh,*sl,*gh,*gl,*fh,*fl,*wih,*wil,*woh,*wol,*f1h,*f1l,*f2h,*f2l;
    cudaGetSymbolAddress((void**)&xbuf, g_xbuf);
    cudaGetSymbolAddress((void**)&zx,   g_zx);
    cudaGetSymbolAddress((void**)&sh, g_sh);  cudaGetSymbolAddress((void**)&sl, g_sl);
    cudaGetSymbolAddress((void**)&gh, g_gh);  cudaGetSymbolAddress((void**)&gl, g_gl);
    cudaGetSymbolAddress((void**)&fh, g_fh);  cudaGetSymbolAddress((void**)&fl, g_fl);
    cudaGetSymbolAddress((void**)&wih, g_wih); cudaGetSymbolAddress((void**)&wil, g_wil);
    cudaGetSymbolAddress((void**)&woh, g_woh); cudaGetSymbolAddress((void**)&wol, g_wol);
    cudaGetSymbolAddress((void**)&f1h, g_f1h); cudaGetSymbolAddress((void**)&f1l, g_f1l);
    cudaGetSymbolAddress((void**)&f2h, g_f2h); cudaGetSymbolAddress((void**)&f2l, g_f2l);

    // one-shot weight conversions (grid-stride)
    wcvt_k<<<1184, 256>>>(W_in, wih, wil, NL*2*DM*DPROJ/4);
    wcvt_k<<<1184, 256>>>(W_out, woh, wol, NL*2*DI*DM/4);
    wcvt_k<<<1184, 256>>>(fw1, f1h, f1l, NL*DM*FFND/4);
    wcvt_k<<<1184, 256>>>(fw2, f2h, f2l, NL*FFND*DM/4);

    copy_k<<<(ROWS*DM + 255)/256, 256>>>(x, xbuf, ROWS*DM);

    for (int l = 0; l < NL; l++){
        // s = (rms(x, nssm) + pos) * mask  -> bf16 hi/lo
        rms512_k<<<ROWS, 128>>>(xbuf, nssm + l*DM, pos, mask, nullptr, sh, sl, 1e-6f);
        // zx[dir] = s @ W_in[l,dir]
        tg2_k<0,128><<<dim3(17, 16, 2), 256>>>(
            sh, sl, wih + (size_t)l*2*DM*DPROJ, wil + (size_t)l*2*DM*DPROJ,
            zx, nullptr, nullptr, ROWS, DPROJ, DM,
            nullptr, nullptr, 0.f, (long)DM*DPROJ, (long)ROWS*DPROJ);
        // conv + silu (both dirs)
        conv_k<<<dim3((ROWS*CONVD + 255)/256, 2), 256>>>(
            conv_w + (size_t)l*2*CONVD*4, conv_b + (size_t)l*2*CONVD);
        // dt / dA
        dt_k<<<dim3((ROWS*NH + 255)/256, 2), 256>>>(
            dt_b + (size_t)l*2*NH, A_log + (size_t)l*2*NH);
        // selective scan (64 chains)
        scan_k<<<64, 64>>>(Dvec + (size_t)l*2*NH);
        // gated norm -> concatenated g (bf16 hi/lo)
        gnorm_k<<<dim3(ROWS, 2), 256>>>(mnw + (size_t)l*2*DI);
        // x += 0.5*mask*(g @ [W_out_f; W_out_b])
        tg2_k<3,64><<<dim3(8, 16, 1), 256>>>(
            gh, gl, woh + (size_t)l*2*DI*DM, wol + (size_t)l*2*DI*DM,
            xbuf, nullptr, nullptr, ROWS, DM, 2*DI,
            nullptr, mask, 0.5f, 0, 0);
        // FFN
        rms512_k<<<ROWS, 128>>>(xbuf, nffn + l*DM, nullptr, nullptr, nullptr, sh, sl, 1e-6f);
        tg2_k<1,128><<<dim3(16, 16, 1), 256>>>(
            sh, sl, f1h + (size_t)l*DM*FFND, f1l + (size_t)l*DM*FFND,
            nullptr, fh, fl, ROWS, FFND, DM,
            fb1 + (size_t)l*FFND, nullptr, 0.f, 0, 0);
        tg2_k<2,64><<<dim3(8, 16, 1), 256>>>(
            fh, fl, f2h + (size_t)l*FFND*DM, f2l + (size_t)l*FFND*DM,
            xbuf, nullptr, nullptr, ROWS, DM, FFND,
            fb2 + (size_t)l*DM, nullptr, 0.f, 0, 0);
    }

    rms512_k<<<ROWS, 128>>>(xbuf, fnw, nullptr, nullptr, (float*)d_out, nullptr, nullptr, 1e-6f);
}